// round 7
// baseline (speedup 1.0000x reference)
#include <cuda_runtime.h>
#include <math.h>

#define Bn 8
#define An 100000
#define Cn 80
#define TOPN 1000
#define MAXOBJ 100
#define CAP 32768
#define MROW 33   // mask row stride in words (bank-conflict-free both directions)

__device__ unsigned g_keys[Bn * An];
__device__ unsigned g_cand[Bn * CAP];
__device__ unsigned g_ccnt[Bn];        // zero-init; reset at end of k_post

// ---------- kernel 1: class-max (4 threads/anchor) + warp-aggregated candidate push ----------
__global__ __launch_bounds__(256) void k_score(const float4* __restrict__ cls4) {
    int T = blockIdx.x * 256 + threadIdx.x;
    int a = T >> 2, r = T & 3;
    const float4* p = cls4 + (size_t)a * 20;
    float m = -1.f;
#pragma unroll
    for (int k = 0; k < 5; ++k) {
        float4 v = __ldg(p + 4 * k + r);
        m = fmaxf(m, fmaxf(fmaxf(v.x, v.y), fmaxf(v.z, v.w)));
    }
    m = fmaxf(m, __shfl_xor_sync(0xffffffffu, m, 1));
    m = fmaxf(m, __shfl_xor_sync(0xffffffffu, m, 2));
    unsigned u = 0xFFFFFFFFu;
    if (r == 0) {
        unsigned bits = __float_as_uint(m);
        if (m > 0.05f) u = (bits < 0x3F800000u) ? (0x3F800000u - bits) : 0u;
        g_keys[a] = u;
    }
    bool cand = (r == 0) && (u < 16380u);
    unsigned msk = __ballot_sync(0xffffffffu, cand);
    if (msk) {
        int b = a / An;                       // warps never straddle images (100000 % 8 == 0)
        int leader = __ffs(msk) - 1;
        unsigned base = 0;
        if ((threadIdx.x & 31) == leader)
            base = atomicAdd(&g_ccnt[b], (unsigned)__popc(msk));
        base = __shfl_sync(0xffffffffu, base, leader);
        if (cand) {
            unsigned p2 = base + __popc(msk & ((1u << (threadIdx.x & 31)) - 1u));
            if (p2 < CAP) g_cand[b * CAP + p2] = (u << 17) | (unsigned)(a - b * An);
        }
    }
}

// ---------- kernel 2: fused select + sort + decode + mask + greedy NMS + output ----------
extern __shared__ unsigned dsm[];   // [0,33792): mask rows; sbox @33792 (float4[1024]); sarea after
__global__ __launch_bounds__(1024) void k_post(const float* __restrict__ cls,
                                               const float4* __restrict__ reg,
                                               const float4* __restrict__ anc,
                                               float* __restrict__ out) {
    __shared__ unsigned hist[4096];            // aliased as sk32 after the cut
    __shared__ unsigned long long sk64[1024];  // fallback keys
    __shared__ unsigned wsum[32];
    __shared__ int s_cut;
    __shared__ unsigned s_tot, s_n;
    __shared__ unsigned s_valid[32], s_kept[32];
    __shared__ int s_base[32];

    unsigned* mask  = dsm;
    float4*   sbox  = (float4*)(dsm + 1024 * MROW);
    float*    sarea = (float*)(dsm + 1024 * MROW + 4096);

    int b = blockIdx.x, tid = threadIdx.x;
    int lane = tid & 31, wid = tid >> 5;

    unsigned ccnt = g_ccnt[b];
    unsigned cc = (ccnt < (unsigned)CAP) ? ccnt : (unsigned)CAP;
    const unsigned* cand = g_cand + b * CAP;

    // init output padding early
    if (tid < MAXOBJ) {
        out[b * MAXOBJ + tid] = -1.f;
        out[Bn * MAXOBJ + b * MAXOBJ + tid] = -1.f;
    }
    if (tid < MAXOBJ * 4) out[2 * Bn * MAXOBJ + b * MAXOBJ * 4 + tid] = 0.f;

    for (int i = tid; i < 4096; i += 1024) hist[i] = 0u;
    if (tid == 0) { s_cut = -1; s_tot = 0u; s_n = 0u; }
    __syncthreads();

    // histogram of u>>2 from candidate list
    for (unsigned c = tid; c < cc; c += 1024)
        atomicAdd(&hist[(cand[c] >> 17) >> 2], 1u);
    __syncthreads();

    // prefix scan over 4096 buckets (4/thread), find cut (cum >= TOPN)
    unsigned h0 = hist[4 * tid], h1 = hist[4 * tid + 1],
             h2 = hist[4 * tid + 2], h3 = hist[4 * tid + 3];
    unsigned s = h0 + h1 + h2 + h3;
    unsigned x = s;
#pragma unroll
    for (int o = 1; o < 32; o <<= 1) {
        unsigned y = __shfl_up_sync(0xffffffffu, x, o);
        if (lane >= o) x += y;
    }
    if (lane == 31) wsum[wid] = x;
    __syncthreads();
    if (tid < 32) {
        unsigned v = wsum[tid];
#pragma unroll
        for (int o = 1; o < 32; o <<= 1) {
            unsigned y = __shfl_up_sync(0xffffffffu, v, o);
            if (tid >= o) v += y;
        }
        wsum[tid] = v;
    }
    __syncthreads();
    unsigned incl = x + (wid ? wsum[wid - 1] : 0u);
    unsigned excl = incl - s;
    if (excl < TOPN && incl >= TOPN) {
        int cut; unsigned c;
        if (excl + h0 >= TOPN)                { cut = 4 * tid;     c = excl + h0; }
        else if (excl + h0 + h1 >= TOPN)      { cut = 4 * tid + 1; c = excl + h0 + h1; }
        else if (excl + h0 + h1 + h2 >= TOPN) { cut = 4 * tid + 2; c = excl + h0 + h1 + h2; }
        else                                  { cut = 4 * tid + 3; c = excl + h0 + h1 + h2 + h3; }
        s_cut = cut; s_tot = c;
    }
    __syncthreads();

    bool fast = (s_cut >= 0) && (s_tot <= 1024u) && (ccnt <= (unsigned)CAP);
    unsigned* sk32 = hist;   // hist fully consumed; reuse first 1024 words

    if (fast) {
        unsigned ulimit = ((unsigned)s_cut + 1u) << 2;
        for (unsigned c = tid; c < cc; c += 1024) {
            unsigned key = cand[c];
            bool sel = (key >> 17) < ulimit;
            unsigned bal = __ballot_sync(__activemask(), sel);
            // warp-aggregated shared atomic
            if (bal) {
                int leader = __ffs(bal) - 1;
                unsigned base = 0;
                if (lane == leader) base = atomicAdd(&s_n, (unsigned)__popc(bal));
                base = __shfl_sync(__activemask(), base, leader);
                if (sel) sk32[base + __popc(bal & ((1u << lane) - 1u))] = key;
            }
        }
        __syncthreads();
        unsigned n = s_n;
        if ((unsigned)tid >= n) sk32[tid] = 0xFFFFFFFFu;
        __syncthreads();
        // bitonic sort 1024 x u32 ascending
        for (int kk = 2; kk <= 1024; kk <<= 1) {
            for (int j = kk >> 1; j > 0; j >>= 1) {
                int ixj = tid ^ j;
                if (ixj > tid) {
                    unsigned a0 = sk32[tid], a1 = sk32[ixj];
                    bool asc = (tid & kk) == 0;
                    if (asc ? (a0 > a1) : (a0 < a1)) { sk32[tid] = a1; sk32[ixj] = a0; }
                }
                __syncthreads();
            }
        }
    } else {
        // cold exact path: bitwise radix select over all keys, 64-bit sort
        const unsigned* keys = g_keys + (size_t)b * An;
        unsigned long long pref = 0ull;
        int rankNeed = TOPN;
        __shared__ unsigned s_c;
        for (int bit = 48; bit >= 0; --bit) {
            if (tid == 0) s_c = 0u;
            __syncthreads();
            unsigned c = 0;
            for (int a = tid; a < An; a += 1024) {
                unsigned long long k = ((unsigned long long)keys[a] << 17) | (unsigned)a;
                if ((k >> (bit + 1)) == pref && !((k >> bit) & 1ull)) c++;
            }
#pragma unroll
            for (int o = 16; o; o >>= 1) c += __shfl_down_sync(0xffffffffu, c, o);
            if (lane == 0) atomicAdd(&s_c, c);
            __syncthreads();
            unsigned C0 = s_c;
            if (rankNeed <= (int)C0) pref <<= 1;
            else { pref = (pref << 1) | 1ull; rankNeed -= (int)C0; }
            __syncthreads();
        }
        for (int a = tid; a < An; a += 1024) {
            unsigned long long k = ((unsigned long long)keys[a] << 17) | (unsigned)a;
            if (k <= pref) {
                unsigned p = atomicAdd(&s_n, 1u);
                if (p < 1024u) sk64[p] = k;
            }
        }
        __syncthreads();
        unsigned n = s_n;
        if ((unsigned)tid >= n) sk64[tid] = ~0ull;
        __syncthreads();
        for (int kk = 2; kk <= 1024; kk <<= 1) {
            for (int j = kk >> 1; j > 0; j >>= 1) {
                int ixj = tid ^ j;
                if (ixj > tid) {
                    unsigned long long a0 = sk64[tid], a1 = sk64[ixj];
                    bool asc = (tid & kk) == 0;
                    if (asc ? (a0 > a1) : (a0 < a1)) { sk64[tid] = a1; sk64[ixj] = a0; }
                }
                __syncthreads();
            }
        }
    }

    // gather + decode; per-thread result regs for output
    float sc = 0.f, clf = 0.f;
    float4 mybox = make_float4(0.f, 0.f, 0.f, 0.f);
    unsigned long long key = fast ? (unsigned long long)sk32[tid] : sk64[tid];
    unsigned n_real = s_n;
    if (tid < TOPN && (unsigned)tid < n_real) {
        int a = (int)(key & 0x1FFFFull);
        unsigned u = (unsigned)(key >> 17);
        sc = (u >= 0x3F800000u) ? 0.f : __uint_as_float(0x3F800000u - u);

        const float4* c4 = reinterpret_cast<const float4*>(cls + ((size_t)b * An + a) * Cn);
        float best = -1.f; int bc = 0;
#pragma unroll
        for (int q = 0; q < Cn / 4; ++q) {
            float4 v = __ldg(c4 + q);
            if (v.x > best) { best = v.x; bc = 4 * q; }
            if (v.y > best) { best = v.y; bc = 4 * q + 1; }
            if (v.z > best) { best = v.z; bc = 4 * q + 2; }
            if (v.w > best) { best = v.w; bc = 4 * q + 3; }
        }
        clf = (float)bc;

        float4 rg = __ldg(reg + (size_t)b * An + a);
        float4 an = __ldg(anc + (size_t)b * An + a);
        float aw  = __fsub_rn(an.z, an.x), ah = __fsub_rn(an.w, an.y);
        float acx = __fadd_rn(an.x, __fmul_rn(0.5f, aw));
        float acy = __fadd_rn(an.y, __fmul_rn(0.5f, ah));
        float pw  = __fmul_rn(expf(rg.z), aw);
        float ph  = __fmul_rn(expf(rg.w), ah);
        float pcx = __fadd_rn(__fmul_rn(rg.x, aw), acx);
        float pcy = __fadd_rn(__fmul_rn(rg.y, ah), acy);
        float hw  = __fmul_rn(0.5f, pw), hh = __fmul_rn(0.5f, ph);
        mybox.x = truncf(__fsub_rn(pcx, hw));
        mybox.y = truncf(__fsub_rn(pcy, hh));
        mybox.z = truncf(__fadd_rn(pcx, hw));
        mybox.w = truncf(__fadd_rn(pcy, hh));

        sbox[tid] = mybox;
        sarea[tid] = fmaxf(__fmul_rn(__fsub_rn(mybox.z, mybox.x), __fsub_rn(mybox.w, mybox.y)), 1e-4f);
    } else {
        sbox[tid] = make_float4(1e9f, 1e9f, 1e9f, 1e9f);
        sarea[tid] = 1e9f;
    }
    bool valid = (tid < TOPN) && (sc > 0.05f);
    unsigned wm = __ballot_sync(0xffffffffu, valid);
    if (lane == 0) s_valid[wid] = wm;
    __syncthreads();

    // suppression mask into dynamic smem (upper-triangle words only), stride MROW
    for (int idx = tid; idx < 32768; idx += 1024) {
        int w = idx >> 10;            // word 0..31 (same across warp)
        int i = idx & 1023;           // row (consecutive across lanes)
        if (i >= TOPN) continue;
        int jbase = w << 5;
        if (jbase + 31 <= i) continue;        // lower-tri word: never read
        float4 bi = sbox[i]; float ai = sarea[i];
        unsigned bits = 0u;
#pragma unroll
        for (int t = 0; t < 32; ++t) {
            float4 bj = sbox[jbase + t]; float aj = sarea[jbase + t];   // broadcast
            float tlx = fmaxf(bi.x, bj.x), tly = fmaxf(bi.y, bj.y);
            float brx = fminf(bi.z, bj.z), bry = fminf(bi.w, bj.w);
            float sx = fmaxf(__fsub_rn(brx, tlx), 0.f);
            float sy = fmaxf(__fsub_rn(bry, tly), 0.f);
            float inter = __fmul_rn(sx, sy);
            // exact: iou >= 0.5  <=>  3*inter >= ai+aj (all integer-valued f32)
            bits |= (__fmul_rn(3.f, inter) >= __fadd_rn(ai, aj)) ? (1u << t) : 0u;
        }
        if (jbase <= i) bits &= ~((2u << (i - jbase)) - 1u);   // drop j <= i in diagonal word
        mask[i * MROW + w] = bits;
    }
    if (tid == 0) g_ccnt[b] = 0u;            // reset for next graph replay
    __syncthreads();

    // early-exit ffs-greedy NMS (warp 0)
    if (tid < 32) {
        unsigned vmask = s_valid[lane];
        unsigned supp = ~vmask;
        unsigned done = 0u, kept = 0u;
        int kcount = 0;
        while (true) {
            unsigned rem = ~supp & ~done;
            unsigned bal = __ballot_sync(0xffffffffu, rem != 0u);
            if (!bal) break;
            int wf = __ffs(bal) - 1;
            unsigned remw = __shfl_sync(0xffffffffu, rem, wf);
            int t = __ffs(remw) - 1;
            int i = wf * 32 + t;
            if (lane == wf) { kept |= (1u << t); done |= (1u << t); }
            if (++kcount >= MAXOBJ) break;   // output full: later kept boxes irrelevant
            unsigned rw = mask[i * MROW + lane];
            supp |= (lane >= (i >> 5)) ? rw : 0u;   // lower-tri words unwritten
        }
        s_kept[lane] = kept;
        int c = __popc(kept), xx = c;
#pragma unroll
        for (int o = 1; o < 32; o <<= 1) {
            int y = __shfl_up_sync(0xffffffffu, xx, o);
            if (lane >= o) xx += y;
        }
        s_base[lane] = xx - c;
    }
    __syncthreads();

    // compaction: kept threads write their registers
    if (tid < TOPN) {
        unsigned kw = s_kept[wid];
        if ((kw >> lane) & 1u) {
            int r = s_base[wid] + __popc(kw & ((1u << lane) - 1u));
            if (r < MAXOBJ) {
                out[b * MAXOBJ + r] = sc;
                out[Bn * MAXOBJ + b * MAXOBJ + r] = clf;
                float* ob = out + 2 * Bn * MAXOBJ + (b * MAXOBJ + r) * 4;
                ob[0] = mybox.x; ob[1] = mybox.y; ob[2] = mybox.z; ob[3] = mybox.w;
            }
        }
    }
}

extern "C" void kernel_launch(void* const* d_in, const int* in_sizes, int n_in,
                              void* d_out, int out_size) {
    const float*  cls = (const float*)d_in[0];
    const float4* reg = (const float4*)d_in[1];
    const float4* anc = (const float4*)d_in[2];
    float* out = (float*)d_out;

    const int dyn = (1024 * MROW) * 4 + 1024 * 16 + 1024 * 4;   // mask + sbox + sarea
    cudaFuncSetAttribute(k_post, cudaFuncAttributeMaxDynamicSharedMemorySize, dyn);

    k_score<<<(Bn * An * 4) / 256, 256>>>((const float4*)cls);
    k_post<<<Bn, 1024, dyn>>>(cls, reg, anc, out);
}

// round 8
// speedup vs baseline: 1.3106x; 1.3106x over previous
#include <cuda_runtime.h>
#include <math.h>

#define Bn 8
#define An 100000
#define Cn 80
#define TOPN 1000
#define MAXOBJ 100
#define CAP 32768

__device__ unsigned g_keys[Bn * An];
__device__ unsigned g_cand[Bn * CAP];
__device__ unsigned g_ccnt[Bn];        // zero-init; reset at end of k_post

// ---------- kernel 1: class-max (4 threads/anchor) + warp-aggregated candidate push ----------
__global__ __launch_bounds__(256) void k_score(const float4* __restrict__ cls4) {
    int T = blockIdx.x * 256 + threadIdx.x;
    int a = T >> 2, r = T & 3;
    const float4* p = cls4 + (size_t)a * 20;
    float m = -1.f;
#pragma unroll
    for (int k = 0; k < 5; ++k) {
        float4 v = __ldg(p + 4 * k + r);
        m = fmaxf(m, fmaxf(fmaxf(v.x, v.y), fmaxf(v.z, v.w)));
    }
    m = fmaxf(m, __shfl_xor_sync(0xffffffffu, m, 1));
    m = fmaxf(m, __shfl_xor_sync(0xffffffffu, m, 2));
    unsigned u = 0xFFFFFFFFu;
    if (r == 0) {
        unsigned bits = __float_as_uint(m);
        if (m > 0.05f) u = (bits < 0x3F800000u) ? (0x3F800000u - bits) : 0u;
        g_keys[a] = u;
    }
    bool cand = (r == 0) && (u < 16380u);
    unsigned msk = __ballot_sync(0xffffffffu, cand);
    if (msk) {
        int b = a / An;                       // warps never straddle images
        int leader = __ffs(msk) - 1;
        unsigned base = 0;
        if ((threadIdx.x & 31) == leader)
            base = atomicAdd(&g_ccnt[b], (unsigned)__popc(msk));
        base = __shfl_sync(0xffffffffu, base, leader);
        if (cand) {
            unsigned p2 = base + __popc(msk & ((1u << (threadIdx.x & 31)) - 1u));
            if (p2 < CAP) g_cand[b * CAP + p2] = (u << 17) | (unsigned)(a - b * An);
        }
    }
}

// ---------- kernel 2: fused select + sort + decode + iterative greedy NMS + output ----------
__global__ __launch_bounds__(1024) void k_post(const float* __restrict__ cls,
                                               const float4* __restrict__ reg,
                                               const float4* __restrict__ anc,
                                               float* __restrict__ out) {
    __shared__ unsigned hist[4096];            // reused: sk32 (fast) / sk64 (fallback)
    __shared__ float4 sbox[1024];
    __shared__ float  sarea[1024];
    __shared__ unsigned wsum[32];
    __shared__ int s_cut;
    __shared__ unsigned s_tot, s_n;
    __shared__ unsigned s_rem[32], s_keptm[32];
    __shared__ int s_base[32];
    __shared__ int s_cur;

    int b = blockIdx.x, tid = threadIdx.x;
    int lane = tid & 31, wid = tid >> 5;

    unsigned ccnt = g_ccnt[b];
    unsigned cc = (ccnt < (unsigned)CAP) ? ccnt : (unsigned)CAP;
    const unsigned* cand = g_cand + b * CAP;

    // init output padding early
    if (tid < MAXOBJ) {
        out[b * MAXOBJ + tid] = -1.f;
        out[Bn * MAXOBJ + b * MAXOBJ + tid] = -1.f;
    }
    if (tid < MAXOBJ * 4) out[2 * Bn * MAXOBJ + b * MAXOBJ * 4 + tid] = 0.f;

    for (int i = tid; i < 4096; i += 1024) hist[i] = 0u;
    if (tid == 0) { s_cut = -1; s_tot = 0u; s_n = 0u; }
    __syncthreads();

    // histogram of u>>2 from candidate list
    for (unsigned c = tid; c < cc; c += 1024)
        atomicAdd(&hist[(cand[c] >> 17) >> 2], 1u);
    __syncthreads();

    // prefix scan over 4096 buckets (4/thread), find cut (cum >= TOPN)
    unsigned h0 = hist[4 * tid], h1 = hist[4 * tid + 1],
             h2 = hist[4 * tid + 2], h3 = hist[4 * tid + 3];
    unsigned s = h0 + h1 + h2 + h3;
    unsigned x = s;
#pragma unroll
    for (int o = 1; o < 32; o <<= 1) {
        unsigned y = __shfl_up_sync(0xffffffffu, x, o);
        if (lane >= o) x += y;
    }
    if (lane == 31) wsum[wid] = x;
    __syncthreads();
    if (tid < 32) {
        unsigned v = wsum[tid];
#pragma unroll
        for (int o = 1; o < 32; o <<= 1) {
            unsigned y = __shfl_up_sync(0xffffffffu, v, o);
            if (tid >= o) v += y;
        }
        wsum[tid] = v;
    }
    __syncthreads();
    unsigned incl = x + (wid ? wsum[wid - 1] : 0u);
    unsigned excl = incl - s;
    if (excl < TOPN && incl >= TOPN) {
        int cut; unsigned c;
        if (excl + h0 >= TOPN)                { cut = 4 * tid;     c = excl + h0; }
        else if (excl + h0 + h1 >= TOPN)      { cut = 4 * tid + 1; c = excl + h0 + h1; }
        else if (excl + h0 + h1 + h2 >= TOPN) { cut = 4 * tid + 2; c = excl + h0 + h1 + h2; }
        else                                  { cut = 4 * tid + 3; c = excl + h0 + h1 + h2 + h3; }
        s_cut = cut; s_tot = c;
    }
    __syncthreads();

    bool fast = (s_cut >= 0) && (s_tot <= 1024u) && (ccnt <= (unsigned)CAP);
    unsigned* sk32 = hist;                                    // fast-path keys
    unsigned long long* sk64 = (unsigned long long*)hist;     // fallback keys (cold)

    if (fast) {
        unsigned ulimit = ((unsigned)s_cut + 1u) << 2;
        for (unsigned c = tid; c < cc; c += 1024) {
            unsigned key = cand[c];
            bool sel = (key >> 17) < ulimit;
            unsigned am = __activemask();
            unsigned bal = __ballot_sync(am, sel);
            if (bal) {
                int leader = __ffs(bal) - 1;
                unsigned base = 0;
                if (lane == leader) base = atomicAdd(&s_n, (unsigned)__popc(bal));
                base = __shfl_sync(am, base, leader);
                if (sel) sk32[base + __popc(bal & ((1u << lane) - 1u))] = key;
            }
        }
        __syncthreads();
        unsigned n = s_n;
        if ((unsigned)tid >= n) sk32[tid] = 0xFFFFFFFFu;
        __syncthreads();
        // bitonic sort 1024 x u32 ascending
        for (int kk = 2; kk <= 1024; kk <<= 1) {
            for (int j = kk >> 1; j > 0; j >>= 1) {
                int ixj = tid ^ j;
                if (ixj > tid) {
                    unsigned a0 = sk32[tid], a1 = sk32[ixj];
                    bool asc = (tid & kk) == 0;
                    if (asc ? (a0 > a1) : (a0 < a1)) { sk32[tid] = a1; sk32[ixj] = a0; }
                }
                __syncthreads();
            }
        }
    } else {
        // cold exact path: bitwise radix select over all keys, 64-bit sort
        const unsigned* keys = g_keys + (size_t)b * An;
        unsigned long long pref = 0ull;
        int rankNeed = TOPN;
        __shared__ unsigned s_c;
        for (int bit = 48; bit >= 0; --bit) {
            if (tid == 0) s_c = 0u;
            __syncthreads();
            unsigned c = 0;
            for (int a = tid; a < An; a += 1024) {
                unsigned long long k = ((unsigned long long)keys[a] << 17) | (unsigned)a;
                if ((k >> (bit + 1)) == pref && !((k >> bit) & 1ull)) c++;
            }
#pragma unroll
            for (int o = 16; o; o >>= 1) c += __shfl_down_sync(0xffffffffu, c, o);
            if (lane == 0) atomicAdd(&s_c, c);
            __syncthreads();
            unsigned C0 = s_c;
            if (rankNeed <= (int)C0) pref <<= 1;
            else { pref = (pref << 1) | 1ull; rankNeed -= (int)C0; }
            __syncthreads();
        }
        for (int a = tid; a < An; a += 1024) {
            unsigned long long k = ((unsigned long long)keys[a] << 17) | (unsigned)a;
            if (k <= pref) {
                unsigned p = atomicAdd(&s_n, 1u);
                if (p < 1024u) sk64[p] = k;
            }
        }
        __syncthreads();
        unsigned n = s_n;
        if ((unsigned)tid >= n) sk64[tid] = ~0ull;
        __syncthreads();
        for (int kk = 2; kk <= 1024; kk <<= 1) {
            for (int j = kk >> 1; j > 0; j >>= 1) {
                int ixj = tid ^ j;
                if (ixj > tid) {
                    unsigned long long a0 = sk64[tid], a1 = sk64[ixj];
                    bool asc = (tid & kk) == 0;
                    if (asc ? (a0 > a1) : (a0 < a1)) { sk64[tid] = a1; sk64[ixj] = a0; }
                }
                __syncthreads();
            }
        }
    }

    // gather + decode; per-thread result regs
    unsigned long long key = fast ? (unsigned long long)sk32[tid] : sk64[tid];
    unsigned n_real = s_n;
    float sc = 0.f, clf = 0.f;
    float4 mybox = make_float4(0.f, 0.f, 0.f, 0.f);
    float myarea = 1e9f;
    if (tid < TOPN && (unsigned)tid < n_real) {
        int a = (int)(key & 0x1FFFFull);
        unsigned u = (unsigned)(key >> 17);
        sc = (u >= 0x3F800000u) ? 0.f : __uint_as_float(0x3F800000u - u);

        const float4* c4 = reinterpret_cast<const float4*>(cls + ((size_t)b * An + a) * Cn);
        float best = -1.f; int bc = 0;
#pragma unroll
        for (int q = 0; q < Cn / 4; ++q) {
            float4 v = __ldg(c4 + q);
            if (v.x > best) { best = v.x; bc = 4 * q; }
            if (v.y > best) { best = v.y; bc = 4 * q + 1; }
            if (v.z > best) { best = v.z; bc = 4 * q + 2; }
            if (v.w > best) { best = v.w; bc = 4 * q + 3; }
        }
        clf = (float)bc;

        float4 rg = __ldg(reg + (size_t)b * An + a);
        float4 an = __ldg(anc + (size_t)b * An + a);
        float aw  = __fsub_rn(an.z, an.x), ah = __fsub_rn(an.w, an.y);
        float acx = __fadd_rn(an.x, __fmul_rn(0.5f, aw));
        float acy = __fadd_rn(an.y, __fmul_rn(0.5f, ah));
        float pw  = __fmul_rn(expf(rg.z), aw);
        float ph  = __fmul_rn(expf(rg.w), ah);
        float pcx = __fadd_rn(__fmul_rn(rg.x, aw), acx);
        float pcy = __fadd_rn(__fmul_rn(rg.y, ah), acy);
        float hw  = __fmul_rn(0.5f, pw), hh = __fmul_rn(0.5f, ph);
        mybox.x = truncf(__fsub_rn(pcx, hw));
        mybox.y = truncf(__fsub_rn(pcy, hh));
        mybox.z = truncf(__fadd_rn(pcx, hw));
        mybox.w = truncf(__fadd_rn(pcy, hh));
        myarea = fmaxf(__fmul_rn(__fsub_rn(mybox.z, mybox.x), __fsub_rn(mybox.w, mybox.y)), 1e-4f);
        sbox[tid] = mybox;
        sarea[tid] = myarea;
    } else {
        sbox[tid] = make_float4(1e9f, 1e9f, 1e9f, 1e9f);
        sarea[tid] = 1e9f;
    }
    bool valid = (tid < TOPN) && (sc > 0.05f);
    bool supp = !valid;        // invalid starts suppressed
    bool kept_self = false;
    unsigned wm = __ballot_sync(0xffffffffu, valid);
    if (lane == 0) s_rem[wid] = wm;
    if (tid < 32) s_keptm[tid] = 0u;
    if (tid == 0) g_ccnt[b] = 0u;           // reset for next graph replay
    __syncthreads();

    // iterative broadcast greedy NMS (early exit at MAXOBJ kept)
    int kcount = 0;
    while (true) {
        // warp 0 finds lowest remaining index, marks kept
        if (tid < 32) {
            unsigned w = s_rem[lane];
            unsigned bal = __ballot_sync(0xffffffffu, w != 0u);
            if (bal == 0u) { if (lane == 0) s_cur = -1; }
            else {
                int wf = __ffs(bal) - 1;
                if (lane == wf) {
                    int t = __ffs(w) - 1;
                    s_cur = wf * 32 + t;
                    s_keptm[wf] |= (1u << t);
                }
            }
        }
        __syncthreads();
        int i = s_cur;
        if (i < 0) break;
        // all threads test own box against kept box i (smem broadcast)
        float4 bi = sbox[i]; float ai = sarea[i];
        if (tid == i) kept_self = true;
        else if (!supp && tid > i) {
            float tlx = fmaxf(bi.x, mybox.x), tly = fmaxf(bi.y, mybox.y);
            float brx = fminf(bi.z, mybox.z), bry = fminf(bi.w, mybox.w);
            float sx = fmaxf(__fsub_rn(brx, tlx), 0.f);
            float sy = fmaxf(__fsub_rn(bry, tly), 0.f);
            float inter = __fmul_rn(sx, sy);
            // exact: iou >= 0.5  <=>  3*inter >= ai+aj (integer-valued f32)
            if (__fmul_rn(3.f, inter) >= __fadd_rn(ai, myarea)) supp = true;
        }
        unsigned w2 = __ballot_sync(0xffffffffu, !supp && !kept_self);
        if (lane == 0) s_rem[wid] = w2;
        if (++kcount >= MAXOBJ) break;      // output full: later kept boxes irrelevant
        __syncthreads();
    }
    __syncthreads();

    // prefix popcount of kept words (warp 0)
    if (tid < 32) {
        unsigned kw = s_keptm[lane];
        int c = __popc(kw), xx = c;
#pragma unroll
        for (int o = 1; o < 32; o <<= 1) {
            int y = __shfl_up_sync(0xffffffffu, xx, o);
            if (lane >= o) xx += y;
        }
        s_base[lane] = xx - c;
    }
    __syncthreads();

    // compaction: kept threads write their registers
    if (tid < TOPN) {
        unsigned kw = s_keptm[wid];
        if ((kw >> lane) & 1u) {
            int r = s_base[wid] + __popc(kw & ((1u << lane) - 1u));
            if (r < MAXOBJ) {
                out[b * MAXOBJ + r] = sc;
                out[Bn * MAXOBJ + b * MAXOBJ + r] = clf;
                float* ob = out + 2 * Bn * MAXOBJ + (b * MAXOBJ + r) * 4;
                ob[0] = mybox.x; ob[1] = mybox.y; ob[2] = mybox.z; ob[3] = mybox.w;
            }
        }
    }
}

extern "C" void kernel_launch(void* const* d_in, const int* in_sizes, int n_in,
                              void* d_out, int out_size) {
    const float*  cls = (const float*)d_in[0];
    const float4* reg = (const float4*)d_in[1];
    const float4* anc = (const float4*)d_in[2];
    float* out = (float*)d_out;

    k_score<<<(Bn * An * 4) / 256, 256>>>((const float4*)cls);
    k_post<<<Bn, 1024>>>(cls, reg, anc, out);
}

// round 9
// speedup vs baseline: 1.4629x; 1.1162x over previous
#include <cuda_runtime.h>
#include <math.h>

#define Bn 8
#define An 100000
#define Cn 80
#define TOPN 1000
#define MAXOBJ 100
#define CAP 32768

__device__ unsigned       g_keys[Bn * An];
__device__ unsigned char  g_class[Bn * An];
__device__ unsigned       g_cand[Bn * CAP];
__device__ unsigned       g_ccnt[Bn];        // zero-init; reset inside k_post

// ---------- kernel 1: class max+argmax (8 threads/anchor) + candidate push ----------
__global__ __launch_bounds__(256) void k_score(const float4* __restrict__ cls4) {
    int T = blockIdx.x * 256 + threadIdx.x;
    int a = T >> 3, r = T & 7;                 // 8 lanes per anchor
    const float4* p = cls4 + (size_t)a * 20;
    float m = -1.f; int mi = 127;
#pragma unroll
    for (int k = 0; k < 3; ++k) {
        int f = k * 8 + r;
        if (f < 20) {
            float4 v = __ldg(p + f);
            int c0 = f * 4;
            if (v.x > m) { m = v.x; mi = c0; }
            if (v.y > m) { m = v.y; mi = c0 + 1; }
            if (v.z > m) { m = v.z; mi = c0 + 2; }
            if (v.w > m) { m = v.w; mi = c0 + 3; }
        }
    }
    // (val, first-idx) reduction over the 8-lane group
#pragma unroll
    for (int o = 1; o < 8; o <<= 1) {
        float om = __shfl_xor_sync(0xffffffffu, m, o);
        int   oi = __shfl_xor_sync(0xffffffffu, mi, o);
        if (om > m || (om == m && oi < mi)) { m = om; mi = oi; }
    }
    unsigned u = 0xFFFFFFFFu;
    if (r == 0) {
        unsigned bits = __float_as_uint(m);
        if (m > 0.05f) u = (bits < 0x3F800000u) ? (0x3F800000u - bits) : 0u;
        g_keys[a] = u;
        g_class[a] = (unsigned char)mi;
    }
    bool cand = (r == 0) && (u < 16380u);
    unsigned msk = __ballot_sync(0xffffffffu, cand);
    if (msk) {
        int b = a / An;                        // warp covers 4 anchors, same image
        int leader = __ffs(msk) - 1;
        unsigned base = 0;
        if ((threadIdx.x & 31) == leader)
            base = atomicAdd(&g_ccnt[b], (unsigned)__popc(msk));
        base = __shfl_sync(0xffffffffu, base, leader);
        if (cand) {
            unsigned p2 = base + __popc(msk & ((1u << (threadIdx.x & 31)) - 1u));
            if (p2 < CAP) g_cand[b * CAP + p2] = (u << 17) | (unsigned)(a - b * An);
        }
    }
}

// ---------- kernel 2: fused select + hybrid sort + decode + 1-barrier greedy ----------
__global__ __launch_bounds__(1024) void k_post(const float4* __restrict__ reg,
                                               const float4* __restrict__ anc,
                                               float* __restrict__ out) {
    __shared__ __align__(16) unsigned hist[4096];   // aliased: sk32 / sk64
    __shared__ float4 sbox[1024];
    __shared__ float  sarea[1024];
    __shared__ unsigned wsum[32];
    __shared__ int s_cut;
    __shared__ unsigned s_tot, s_n;
    __shared__ unsigned s_rem[2][32], s_keptm[32];
    __shared__ int s_base[32];

    int b = blockIdx.x, tid = threadIdx.x;
    int lane = tid & 31, wid = tid >> 5;

    unsigned ccnt = g_ccnt[b];
    unsigned cc = (ccnt < (unsigned)CAP) ? ccnt : (unsigned)CAP;
    const unsigned* cand = g_cand + b * CAP;

    if (tid < MAXOBJ) {
        out[b * MAXOBJ + tid] = -1.f;
        out[Bn * MAXOBJ + b * MAXOBJ + tid] = -1.f;
    }
    if (tid < MAXOBJ * 4) out[2 * Bn * MAXOBJ + b * MAXOBJ * 4 + tid] = 0.f;

    for (int i = tid; i < 4096; i += 1024) hist[i] = 0u;
    if (tid == 0) { s_cut = -1; s_tot = 0u; s_n = 0u; }
    __syncthreads();

    for (unsigned c = tid; c < cc; c += 1024)
        atomicAdd(&hist[(cand[c] >> 17) >> 2], 1u);
    __syncthreads();

    // prefix scan over 4096 buckets (4/thread), find cut (cum >= TOPN)
    unsigned h0 = hist[4 * tid], h1 = hist[4 * tid + 1],
             h2 = hist[4 * tid + 2], h3 = hist[4 * tid + 3];
    unsigned s = h0 + h1 + h2 + h3;
    unsigned x = s;
#pragma unroll
    for (int o = 1; o < 32; o <<= 1) {
        unsigned y = __shfl_up_sync(0xffffffffu, x, o);
        if (lane >= o) x += y;
    }
    if (lane == 31) wsum[wid] = x;
    __syncthreads();
    if (tid < 32) {
        unsigned v = wsum[tid];
#pragma unroll
        for (int o = 1; o < 32; o <<= 1) {
            unsigned y = __shfl_up_sync(0xffffffffu, v, o);
            if (tid >= o) v += y;
        }
        wsum[tid] = v;
    }
    __syncthreads();
    unsigned incl = x + (wid ? wsum[wid - 1] : 0u);
    unsigned excl = incl - s;
    if (excl < TOPN && incl >= TOPN) {
        int cut; unsigned c;
        if (excl + h0 >= TOPN)                { cut = 4 * tid;     c = excl + h0; }
        else if (excl + h0 + h1 >= TOPN)      { cut = 4 * tid + 1; c = excl + h0 + h1; }
        else if (excl + h0 + h1 + h2 >= TOPN) { cut = 4 * tid + 2; c = excl + h0 + h1 + h2; }
        else                                  { cut = 4 * tid + 3; c = excl + h0 + h1 + h2 + h3; }
        s_cut = cut; s_tot = c;
    }
    __syncthreads();

    bool fast = (s_cut >= 0) && (s_tot <= 1024u) && (ccnt <= (unsigned)CAP);
    unsigned* sk32 = hist;
    unsigned long long* sk64 = (unsigned long long*)hist;
    unsigned long long key = ~0ull;

    if (fast) {
        unsigned ulimit = ((unsigned)s_cut + 1u) << 2;
        for (unsigned c = tid; c < cc; c += 1024) {
            unsigned k2 = cand[c];
            bool sel = (k2 >> 17) < ulimit;
            unsigned am = __activemask();
            unsigned bal = __ballot_sync(am, sel);
            if (bal) {
                int leader = __ffs(bal) - 1;
                unsigned base = 0;
                if (lane == leader) base = atomicAdd(&s_n, (unsigned)__popc(bal));
                base = __shfl_sync(am, base, leader);
                if (sel) sk32[base + __popc(bal & ((1u << lane) - 1u))] = k2;
            }
        }
        __syncthreads();
        unsigned n = s_n;
        unsigned v = (tid < (int)n) ? sk32[tid] : 0xFFFFFFFFu;
        __syncthreads();
        // hybrid bitonic: in-warp stages via shfl, cross-warp via smem (2 barriers)
#pragma unroll
        for (int kk = 2; kk <= 32; kk <<= 1) {
            for (int j = kk >> 1; j > 0; j >>= 1) {
                unsigned o = __shfl_xor_sync(0xffffffffu, v, j);
                bool keepmin = ((tid & kk) == 0) == ((tid & j) == 0);
                v = keepmin ? (v < o ? v : o) : (v > o ? v : o);
            }
        }
        for (int kk = 64; kk <= 1024; kk <<= 1) {
            for (int j = kk >> 1; j >= 32; j >>= 1) {
                sk32[tid] = v;
                __syncthreads();
                unsigned o = sk32[tid ^ j];
                __syncthreads();
                bool keepmin = ((tid & kk) == 0) == ((tid & j) == 0);
                v = keepmin ? (v < o ? v : o) : (v > o ? v : o);
            }
#pragma unroll
            for (int j = 16; j > 0; j >>= 1) {
                unsigned o = __shfl_xor_sync(0xffffffffu, v, j);
                bool keepmin = ((tid & kk) == 0) == ((tid & j) == 0);
                v = keepmin ? (v < o ? v : o) : (v > o ? v : o);
            }
        }
        key = (unsigned long long)v;
    } else {
        // cold exact path: bitwise radix select over all keys + smem 64-bit bitonic
        const unsigned* keys = g_keys + (size_t)b * An;
        unsigned long long pref = 0ull;
        int rankNeed = TOPN;
        __shared__ unsigned s_c;
        for (int bit = 48; bit >= 0; --bit) {
            if (tid == 0) s_c = 0u;
            __syncthreads();
            unsigned c = 0;
            for (int a = tid; a < An; a += 1024) {
                unsigned long long k = ((unsigned long long)keys[a] << 17) | (unsigned)a;
                if ((k >> (bit + 1)) == pref && !((k >> bit) & 1ull)) c++;
            }
#pragma unroll
            for (int o = 16; o; o >>= 1) c += __shfl_down_sync(0xffffffffu, c, o);
            if (lane == 0) atomicAdd(&s_c, c);
            __syncthreads();
            unsigned C0 = s_c;
            if (rankNeed <= (int)C0) pref <<= 1;
            else { pref = (pref << 1) | 1ull; rankNeed -= (int)C0; }
            __syncthreads();
        }
        for (int a = tid; a < An; a += 1024) {
            unsigned long long k = ((unsigned long long)keys[a] << 17) | (unsigned)a;
            if (k <= pref) {
                unsigned p = atomicAdd(&s_n, 1u);
                if (p < 1024u) sk64[p] = k;
            }
        }
        __syncthreads();
        unsigned n = s_n;
        if ((unsigned)tid >= n) sk64[tid] = ~0ull;
        __syncthreads();
        for (int kk = 2; kk <= 1024; kk <<= 1) {
            for (int j = kk >> 1; j > 0; j >>= 1) {
                int ixj = tid ^ j;
                if (ixj > tid) {
                    unsigned long long a0 = sk64[tid], a1 = sk64[ixj];
                    bool asc = (tid & kk) == 0;
                    if (asc ? (a0 > a1) : (a0 < a1)) { sk64[tid] = a1; sk64[ixj] = a0; }
                }
                __syncthreads();
            }
        }
        key = sk64[tid];
    }

    // gather + decode into registers (no cls reads — class from g_class)
    unsigned n_real = s_n;
    float sc = 0.f, clf = 0.f;
    float4 mybox = make_float4(0.f, 0.f, 0.f, 0.f);
    float myarea = 1e9f;
    if (tid < TOPN && (unsigned)tid < n_real) {
        int a = (int)(key & 0x1FFFFull);
        unsigned u = (unsigned)(key >> 17);
        sc = (u >= 0x3F800000u) ? 0.f : __uint_as_float(0x3F800000u - u);
        clf = (float)g_class[(size_t)b * An + a];

        float4 rg = __ldg(reg + (size_t)b * An + a);
        float4 an = __ldg(anc + (size_t)b * An + a);
        float aw  = __fsub_rn(an.z, an.x), ah = __fsub_rn(an.w, an.y);
        float acx = __fadd_rn(an.x, __fmul_rn(0.5f, aw));
        float acy = __fadd_rn(an.y, __fmul_rn(0.5f, ah));
        float pw  = __fmul_rn(expf(rg.z), aw);
        float ph  = __fmul_rn(expf(rg.w), ah);
        float pcx = __fadd_rn(__fmul_rn(rg.x, aw), acx);
        float pcy = __fadd_rn(__fmul_rn(rg.y, ah), acy);
        float hw  = __fmul_rn(0.5f, pw), hh = __fmul_rn(0.5f, ph);
        mybox.x = truncf(__fsub_rn(pcx, hw));
        mybox.y = truncf(__fsub_rn(pcy, hh));
        mybox.z = truncf(__fadd_rn(pcx, hw));
        mybox.w = truncf(__fadd_rn(pcy, hh));
        myarea = fmaxf(__fmul_rn(__fsub_rn(mybox.z, mybox.x), __fsub_rn(mybox.w, mybox.y)), 1e-4f);
        sbox[tid] = mybox;
        sarea[tid] = myarea;
    } else {
        sbox[tid] = make_float4(1e9f, 1e9f, 1e9f, 1e9f);
        sarea[tid] = 1e9f;
    }
    bool valid = (tid < TOPN) && (sc > 0.05f);
    bool supp = !valid;
    bool kept_self = false;
    unsigned wm = __ballot_sync(0xffffffffu, valid);
    if (lane == 0) s_rem[0][wid] = wm;
    if (tid < 32) s_keptm[tid] = 0u;
    if (tid == 0) g_ccnt[b] = 0u;               // reset for next graph replay
    __syncthreads();

    // one-barrier greedy NMS, double-buffered remaining-mask (race-free)
    int cur = 0, kcount = 0;
    while (true) {
        unsigned w = s_rem[cur][lane];          // consistent snapshot
        unsigned bal = __ballot_sync(0xffffffffu, w != 0u);
        if (!bal) break;
        int wf = __ffs(bal) - 1;
        unsigned ww = __shfl_sync(0xffffffffu, w, wf);
        int i = (wf << 5) + __ffs(ww) - 1;      // lowest remaining = next kept
        if (tid == i) { kept_self = true; s_keptm[wid] |= (1u << lane); }
        if (!supp && !kept_self && tid > i) {
            float4 bi = sbox[i]; float ai = sarea[i];
            float tlx = fmaxf(bi.x, mybox.x), tly = fmaxf(bi.y, mybox.y);
            float brx = fminf(bi.z, mybox.z), bry = fminf(bi.w, mybox.w);
            float sx = fmaxf(__fsub_rn(brx, tlx), 0.f);
            float sy = fmaxf(__fsub_rn(bry, tly), 0.f);
            float inter = __fmul_rn(sx, sy);
            // exact: iou >= 0.5  <=>  3*inter >= ai+aj (integer-valued f32)
            if (__fmul_rn(3.f, inter) >= __fadd_rn(ai, myarea)) supp = true;
        }
        unsigned w2 = __ballot_sync(0xffffffffu, !supp && !kept_self);
        if (lane == 0) s_rem[cur ^ 1][wid] = w2;
        if (++kcount >= MAXOBJ) break;          // output full: rest irrelevant
        __syncthreads();
        cur ^= 1;
    }
    __syncthreads();

    if (tid < 32) {
        unsigned kw = s_keptm[lane];
        int c = __popc(kw), xx = c;
#pragma unroll
        for (int o = 1; o < 32; o <<= 1) {
            int y = __shfl_up_sync(0xffffffffu, xx, o);
            if (lane >= o) xx += y;
        }
        s_base[lane] = xx - c;
    }
    __syncthreads();

    if (tid < TOPN) {
        unsigned kw = s_keptm[wid];
        if ((kw >> lane) & 1u) {
            int r = s_base[wid] + __popc(kw & ((1u << lane) - 1u));
            if (r < MAXOBJ) {
                out[b * MAXOBJ + r] = sc;
                out[Bn * MAXOBJ + b * MAXOBJ + r] = clf;
                float* ob = out + 2 * Bn * MAXOBJ + (b * MAXOBJ + r) * 4;
                ob[0] = mybox.x; ob[1] = mybox.y; ob[2] = mybox.z; ob[3] = mybox.w;
            }
        }
    }
}

extern "C" void kernel_launch(void* const* d_in, const int* in_sizes, int n_in,
                              void* d_out, int out_size) {
    const float*  cls = (const float*)d_in[0];
    const float4* reg = (const float4*)d_in[1];
    const float4* anc = (const float4*)d_in[2];
    float* out = (float*)d_out;

    k_score<<<(Bn * An * 8) / 256, 256>>>((const float4*)cls);
    k_post<<<Bn, 1024>>>(reg, anc, out);
}

// round 10
// speedup vs baseline: 1.5338x; 1.0485x over previous
#include <cuda_runtime.h>
#include <math.h>

#define Bn 8
#define An 100000
#define Cn 80
#define TOPN 1000
#define MAXOBJ 100
#define CAP 32768

__device__ unsigned       g_keys[Bn * An];
__device__ unsigned char  g_class[Bn * An];
__device__ unsigned       g_cand[Bn * CAP];
__device__ unsigned       g_ccnt[Bn];        // zero-init; reset inside k_post

#define ARGM(v, base, m, mi) \
    do { \
        if ((v).x > (m)) { (m) = (v).x; (mi) = (base); } \
        if ((v).y > (m)) { (m) = (v).y; (mi) = (base) + 1; } \
        if ((v).z > (m)) { (m) = (v).z; (mi) = (base) + 2; } \
        if ((v).w > (m)) { (m) = (v).w; (mi) = (base) + 3; } \
    } while (0)

// ---------- kernel 1: 2 anchors/thread, 8 lanes/anchor, streaming loads ----------
__global__ __launch_bounds__(256) void k_score(const float4* __restrict__ cls4) {
    int T = blockIdx.x * 256 + threadIdx.x;
    int pr = T >> 3, r = T & 7;          // pair id, lane-in-group
    int a0 = pr * 2;                     // anchors a0, a0+1 (same image)
    const float4* p0 = cls4 + (size_t)a0 * 20;

    // independent loads, issued up front (MLP 4-6)
    float4 x0 = __ldcs(p0 + r);
    float4 x1 = __ldcs(p0 + 8 + r);
    float4 y0 = __ldcs(p0 + 20 + r);
    float4 y1 = __ldcs(p0 + 28 + r);
    float4 x2, y2;
    bool third = (r < 4);
    if (third) { x2 = __ldcs(p0 + 16 + r); y2 = __ldcs(p0 + 36 + r); }

    float m0 = -1.f, m1 = -1.f; int i0 = 127, i1 = 127;
    ARGM(x0, 4 * r,       m0, i0);
    ARGM(x1, 32 + 4 * r,  m0, i0);
    if (third) ARGM(x2, 64 + 4 * r, m0, i0);
    ARGM(y0, 4 * r,       m1, i1);
    ARGM(y1, 32 + 4 * r,  m1, i1);
    if (third) ARGM(y2, 64 + 4 * r, m1, i1);

    // interleaved (val, first-idx) reduction over the 8-lane group
#pragma unroll
    for (int o = 1; o < 8; o <<= 1) {
        float om0 = __shfl_xor_sync(0xffffffffu, m0, o);
        int   oi0 = __shfl_xor_sync(0xffffffffu, i0, o);
        float om1 = __shfl_xor_sync(0xffffffffu, m1, o);
        int   oi1 = __shfl_xor_sync(0xffffffffu, i1, o);
        if (om0 > m0 || (om0 == m0 && oi0 < i0)) { m0 = om0; i0 = oi0; }
        if (om1 > m1 || (om1 == m1 && oi1 < i1)) { m1 = om1; i1 = oi1; }
    }
    unsigned b0 = __float_as_uint(m0), b1 = __float_as_uint(m1);
    unsigned u0 = (m0 > 0.05f) ? ((b0 < 0x3F800000u) ? (0x3F800000u - b0) : 0u) : 0xFFFFFFFFu;
    unsigned u1 = (m1 > 0.05f) ? ((b1 < 0x3F800000u) ? (0x3F800000u - b1) : 0u) : 0xFFFFFFFFu;

    if (r == 0) {
        *reinterpret_cast<uint2*>(&g_keys[a0]) = make_uint2(u0, u1);
        *reinterpret_cast<unsigned short*>(&g_class[a0]) =
            (unsigned short)((unsigned)i0 | ((unsigned)i1 << 8));
    }

    // fused warp-aggregated candidate push (both anchor slots)
    unsigned msk0 = __ballot_sync(0xffffffffu, (r == 0) && u0 < 16380u);
    unsigned msk1 = __ballot_sync(0xffffffffu, (r == 0) && u1 < 16380u);
    unsigned tot = (unsigned)(__popc(msk0) + __popc(msk1));
    if (tot) {
        int b = a0 / An;                 // warp = 4 pairs, never straddles images
        int leader = __ffs(msk0 | msk1) - 1;
        unsigned base = 0;
        if ((threadIdx.x & 31) == leader) base = atomicAdd(&g_ccnt[b], tot);
        base = __shfl_sync(0xffffffffu, base, leader);
        if (r == 0) {
            unsigned lanebit = 1u << (threadIdx.x & 31);
            int al = a0 - b * An;
            if (u0 < 16380u) {
                unsigned p = base + (unsigned)__popc(msk0 & (lanebit - 1u));
                if (p < CAP) g_cand[b * CAP + p] = (u0 << 17) | (unsigned)al;
            }
            if (u1 < 16380u) {
                unsigned p = base + (unsigned)__popc(msk0)
                           + (unsigned)__popc(msk1 & (lanebit - 1u));
                if (p < CAP) g_cand[b * CAP + p] = (u1 << 17) | (unsigned)(al + 1);
            }
        }
    }
}

// ---------- kernel 2: fused select + hybrid sort + decode + 1-ballot greedy ----------
__global__ __launch_bounds__(1024) void k_post(const float4* __restrict__ reg,
                                               const float4* __restrict__ anc,
                                               float* __restrict__ out) {
    __shared__ __align__(16) unsigned hist[4096];   // aliased: sk32 / sk64
    __shared__ float4 sbox[1024];
    __shared__ float  sarea[1024];
    __shared__ unsigned wsum[32];
    __shared__ int s_cut;
    __shared__ unsigned s_tot, s_n;
    __shared__ unsigned s_rem[32], s_keptm[32];
    __shared__ int s_base[32];

    int b = blockIdx.x, tid = threadIdx.x;
    int lane = tid & 31, wid = tid >> 5;

    unsigned ccnt = g_ccnt[b];
    unsigned cc = (ccnt < (unsigned)CAP) ? ccnt : (unsigned)CAP;
    const unsigned* cand = g_cand + b * CAP;

    if (tid < MAXOBJ) {
        out[b * MAXOBJ + tid] = -1.f;
        out[Bn * MAXOBJ + b * MAXOBJ + tid] = -1.f;
    }
    if (tid < MAXOBJ * 4) out[2 * Bn * MAXOBJ + b * MAXOBJ * 4 + tid] = 0.f;

    for (int i = tid; i < 4096; i += 1024) hist[i] = 0u;
    if (tid == 0) { s_cut = -1; s_tot = 0u; s_n = 0u; }
    __syncthreads();

    for (unsigned c = tid; c < cc; c += 1024)
        atomicAdd(&hist[(cand[c] >> 17) >> 2], 1u);
    __syncthreads();

    // prefix scan over 4096 buckets (4/thread), find cut (cum >= TOPN)
    unsigned h0 = hist[4 * tid], h1 = hist[4 * tid + 1],
             h2 = hist[4 * tid + 2], h3 = hist[4 * tid + 3];
    unsigned s = h0 + h1 + h2 + h3;
    unsigned x = s;
#pragma unroll
    for (int o = 1; o < 32; o <<= 1) {
        unsigned y = __shfl_up_sync(0xffffffffu, x, o);
        if (lane >= o) x += y;
    }
    if (lane == 31) wsum[wid] = x;
    __syncthreads();
    if (tid < 32) {
        unsigned v = wsum[tid];
#pragma unroll
        for (int o = 1; o < 32; o <<= 1) {
            unsigned y = __shfl_up_sync(0xffffffffu, v, o);
            if (tid >= o) v += y;
        }
        wsum[tid] = v;
    }
    __syncthreads();
    unsigned incl = x + (wid ? wsum[wid - 1] : 0u);
    unsigned excl = incl - s;
    if (excl < TOPN && incl >= TOPN) {
        int cut; unsigned c;
        if (excl + h0 >= TOPN)                { cut = 4 * tid;     c = excl + h0; }
        else if (excl + h0 + h1 >= TOPN)      { cut = 4 * tid + 1; c = excl + h0 + h1; }
        else if (excl + h0 + h1 + h2 >= TOPN) { cut = 4 * tid + 2; c = excl + h0 + h1 + h2; }
        else                                  { cut = 4 * tid + 3; c = excl + h0 + h1 + h2 + h3; }
        s_cut = cut; s_tot = c;
    }
    __syncthreads();

    bool fast = (s_cut >= 0) && (s_tot <= 1024u) && (ccnt <= (unsigned)CAP);
    unsigned* sk32 = hist;
    unsigned long long* sk64 = (unsigned long long*)hist;
    unsigned long long key = ~0ull;

    if (fast) {
        unsigned ulimit = ((unsigned)s_cut + 1u) << 2;
        for (unsigned c = tid; c < cc; c += 1024) {
            unsigned k2 = cand[c];
            bool sel = (k2 >> 17) < ulimit;
            unsigned am = __activemask();
            unsigned bal = __ballot_sync(am, sel);
            if (bal) {
                int leader = __ffs(bal) - 1;
                unsigned base = 0;
                if (lane == leader) base = atomicAdd(&s_n, (unsigned)__popc(bal));
                base = __shfl_sync(am, base, leader);
                if (sel) sk32[base + __popc(bal & ((1u << lane) - 1u))] = k2;
            }
        }
        __syncthreads();
        unsigned n = s_n;
        unsigned v = (tid < (int)n) ? sk32[tid] : 0xFFFFFFFFu;
        __syncthreads();
        // hybrid bitonic: in-warp via shfl, cross-warp via smem
#pragma unroll
        for (int kk = 2; kk <= 32; kk <<= 1) {
            for (int j = kk >> 1; j > 0; j >>= 1) {
                unsigned o = __shfl_xor_sync(0xffffffffu, v, j);
                bool keepmin = ((tid & kk) == 0) == ((tid & j) == 0);
                v = keepmin ? (v < o ? v : o) : (v > o ? v : o);
            }
        }
        for (int kk = 64; kk <= 1024; kk <<= 1) {
            for (int j = kk >> 1; j >= 32; j >>= 1) {
                sk32[tid] = v;
                __syncthreads();
                unsigned o = sk32[tid ^ j];
                __syncthreads();
                bool keepmin = ((tid & kk) == 0) == ((tid & j) == 0);
                v = keepmin ? (v < o ? v : o) : (v > o ? v : o);
            }
#pragma unroll
            for (int j = 16; j > 0; j >>= 1) {
                unsigned o = __shfl_xor_sync(0xffffffffu, v, j);
                bool keepmin = ((tid & kk) == 0) == ((tid & j) == 0);
                v = keepmin ? (v < o ? v : o) : (v > o ? v : o);
            }
        }
        key = (unsigned long long)v;
    } else {
        // cold exact path: bitwise radix select over all keys + smem 64-bit bitonic
        const unsigned* keys = g_keys + (size_t)b * An;
        unsigned long long pref = 0ull;
        int rankNeed = TOPN;
        __shared__ unsigned s_c;
        for (int bit = 48; bit >= 0; --bit) {
            if (tid == 0) s_c = 0u;
            __syncthreads();
            unsigned c = 0;
            for (int a = tid; a < An; a += 1024) {
                unsigned long long k = ((unsigned long long)keys[a] << 17) | (unsigned)a;
                if ((k >> (bit + 1)) == pref && !((k >> bit) & 1ull)) c++;
            }
#pragma unroll
            for (int o = 16; o; o >>= 1) c += __shfl_down_sync(0xffffffffu, c, o);
            if (lane == 0) atomicAdd(&s_c, c);
            __syncthreads();
            unsigned C0 = s_c;
            if (rankNeed <= (int)C0) pref <<= 1;
            else { pref = (pref << 1) | 1ull; rankNeed -= (int)C0; }
            __syncthreads();
        }
        for (int a = tid; a < An; a += 1024) {
            unsigned long long k = ((unsigned long long)keys[a] << 17) | (unsigned)a;
            if (k <= pref) {
                unsigned p = atomicAdd(&s_n, 1u);
                if (p < 1024u) sk64[p] = k;
            }
        }
        __syncthreads();
        unsigned n = s_n;
        if ((unsigned)tid >= n) sk64[tid] = ~0ull;
        __syncthreads();
        for (int kk = 2; kk <= 1024; kk <<= 1) {
            for (int j = kk >> 1; j > 0; j >>= 1) {
                int ixj = tid ^ j;
                if (ixj > tid) {
                    unsigned long long a0 = sk64[tid], a1 = sk64[ixj];
                    bool asc = (tid & kk) == 0;
                    if (asc ? (a0 > a1) : (a0 < a1)) { sk64[tid] = a1; sk64[ixj] = a0; }
                }
                __syncthreads();
            }
        }
        key = sk64[tid];
    }

    // gather + decode into registers
    unsigned n_real = s_n;
    float sc = 0.f, clf = 0.f;
    float4 mybox = make_float4(0.f, 0.f, 0.f, 0.f);
    float myarea = 1e9f;
    if (tid < TOPN && (unsigned)tid < n_real) {
        int a = (int)(key & 0x1FFFFull);
        unsigned u = (unsigned)(key >> 17);
        sc = (u >= 0x3F800000u) ? 0.f : __uint_as_float(0x3F800000u - u);
        clf = (float)g_class[(size_t)b * An + a];

        float4 rg = __ldg(reg + (size_t)b * An + a);
        float4 an = __ldg(anc + (size_t)b * An + a);
        float aw  = __fsub_rn(an.z, an.x), ah = __fsub_rn(an.w, an.y);
        float acx = __fadd_rn(an.x, __fmul_rn(0.5f, aw));
        float acy = __fadd_rn(an.y, __fmul_rn(0.5f, ah));
        float pw  = __fmul_rn(expf(rg.z), aw);
        float ph  = __fmul_rn(expf(rg.w), ah);
        float pcx = __fadd_rn(__fmul_rn(rg.x, aw), acx);
        float pcy = __fadd_rn(__fmul_rn(rg.y, ah), acy);
        float hw  = __fmul_rn(0.5f, pw), hh = __fmul_rn(0.5f, ph);
        mybox.x = truncf(__fsub_rn(pcx, hw));
        mybox.y = truncf(__fsub_rn(pcy, hh));
        mybox.z = truncf(__fadd_rn(pcx, hw));
        mybox.w = truncf(__fadd_rn(pcy, hh));
        myarea = fmaxf(__fmul_rn(__fsub_rn(mybox.z, mybox.x), __fsub_rn(mybox.w, mybox.y)), 1e-4f);
        sbox[tid] = mybox;
        sarea[tid] = myarea;
    } else {
        sbox[tid] = make_float4(1e9f, 1e9f, 1e9f, 1e9f);
        sarea[tid] = 1e9f;
    }
    bool valid = (tid < TOPN) && (sc > 0.05f);
    bool supp = !valid;
    unsigned wm = __ballot_sync(0xffffffffu, valid);
    if (lane == 0) s_rem[wid] = wm;
    if (tid < 32) s_keptm[tid] = 0u;
    if (tid == 0) g_ccnt[b] = 0u;               // reset for next graph replay
    __syncthreads();

    // greedy NMS: 1 ballot + 1 barrier per iteration; eager atomic bit-clears
    int kcount = 0;
    while (true) {
        unsigned w = s_rem[lane];               // post-barrier snapshot (all 32 words/warp)
        unsigned bal = __ballot_sync(0xffffffffu, w != 0u);
        if (!bal) break;
        int wf = __ffs(bal) - 1;
        unsigned ww = __shfl_sync(0xffffffffu, w, wf);
        int i = (wf << 5) + __ffs(ww) - 1;      // lowest remaining = next kept (unsuppressed by construction)
        if (tid == i) {
            s_keptm[wid] |= (1u << lane);       // sole writer this iteration
            atomicAnd(&s_rem[wid], ~(1u << lane));
        } else if (!supp && tid > i) {
            float4 bi = sbox[i]; float ai = sarea[i];   // smem broadcast
            float tlx = fmaxf(bi.x, mybox.x), tly = fmaxf(bi.y, mybox.y);
            float brx = fminf(bi.z, mybox.z), bry = fminf(bi.w, mybox.w);
            float sx = fmaxf(__fsub_rn(brx, tlx), 0.f);
            float sy = fmaxf(__fsub_rn(bry, tly), 0.f);
            float inter = __fmul_rn(sx, sy);
            // exact: iou >= 0.5  <=>  3*inter >= ai+aj (integer-valued f32)
            if (__fmul_rn(3.f, inter) >= __fadd_rn(ai, myarea)) {
                supp = true;
                atomicAnd(&s_rem[wid], ~(1u << lane));
            }
        }
        if (++kcount >= MAXOBJ) break;          // output full: rest irrelevant
        __syncthreads();
    }
    __syncthreads();

    if (tid < 32) {
        unsigned kw = s_keptm[lane];
        int c = __popc(kw), xx = c;
#pragma unroll
        for (int o = 1; o < 32; o <<= 1) {
            int y = __shfl_up_sync(0xffffffffu, xx, o);
            if (lane >= o) xx += y;
        }
        s_base[lane] = xx - c;
    }
    __syncthreads();

    if (tid < TOPN) {
        unsigned kw = s_keptm[wid];
        if ((kw >> lane) & 1u) {
            int r = s_base[wid] + __popc(kw & ((1u << lane) - 1u));
            if (r < MAXOBJ) {
                out[b * MAXOBJ + r] = sc;
                out[Bn * MAXOBJ + b * MAXOBJ + r] = clf;
                float* ob = out + 2 * Bn * MAXOBJ + (b * MAXOBJ + r) * 4;
                ob[0] = mybox.x; ob[1] = mybox.y; ob[2] = mybox.z; ob[3] = mybox.w;
            }
        }
    }
}

extern "C" void kernel_launch(void* const* d_in, const int* in_sizes, int n_in,
                              void* d_out, int out_size) {
    const float*  cls = (const float*)d_in[0];
    const float4* reg = (const float4*)d_in[1];
    const float4* anc = (const float4*)d_in[2];
    float* out = (float*)d_out;

    k_score<<<(Bn * An / 2 * 8) / 256, 256>>>((const float4*)cls);
    k_post<<<Bn, 1024>>>(reg, anc, out);
}

// round 11
// speedup vs baseline: 1.7377x; 1.1329x over previous
#include <cuda_runtime.h>
#include <math.h>

#define Bn 8
#define An 100000
#define Cn 80
#define TOPN 1000
#define MAXOBJ 100
#define CAP 32768

__device__ unsigned       g_keys[Bn * An];
__device__ unsigned char  g_class[Bn * An];
__device__ unsigned       g_cand[Bn * CAP];
__device__ unsigned       g_ccnt[Bn];        // zero-init; reset inside k_post

#define ARGM(v, base, m, mi) \
    do { \
        if ((v).x > (m)) { (m) = (v).x; (mi) = (base); } \
        if ((v).y > (m)) { (m) = (v).y; (mi) = (base) + 1; } \
        if ((v).z > (m)) { (m) = (v).z; (mi) = (base) + 2; } \
        if ((v).w > (m)) { (m) = (v).w; (mi) = (base) + 3; } \
    } while (0)

// exact: iou >= 0.5  <=>  3*inter >= ai+aj (all quantities integer-valued f32)
__device__ __forceinline__ bool iou_ge(float4 bi, float ai, float4 bj, float aj) {
    float tlx = fmaxf(bi.x, bj.x), tly = fmaxf(bi.y, bj.y);
    float brx = fminf(bi.z, bj.z), bry = fminf(bi.w, bj.w);
    float sx = fmaxf(__fsub_rn(brx, tlx), 0.f);
    float sy = fmaxf(__fsub_rn(bry, tly), 0.f);
    float inter = __fmul_rn(sx, sy);
    return __fmul_rn(3.f, inter) >= __fadd_rn(ai, aj);
}

// ---------- kernel 1: 2 anchors/thread, 8 lanes/anchor, streaming loads ----------
__global__ __launch_bounds__(256) void k_score(const float4* __restrict__ cls4) {
    int T = blockIdx.x * 256 + threadIdx.x;
    int pr = T >> 3, r = T & 7;
    int a0 = pr * 2;
    const float4* p0 = cls4 + (size_t)a0 * 20;

    float4 x0 = __ldcs(p0 + r);
    float4 x1 = __ldcs(p0 + 8 + r);
    float4 y0 = __ldcs(p0 + 20 + r);
    float4 y1 = __ldcs(p0 + 28 + r);
    float4 x2, y2;
    bool third = (r < 4);
    if (third) { x2 = __ldcs(p0 + 16 + r); y2 = __ldcs(p0 + 36 + r); }

    float m0 = -1.f, m1 = -1.f; int i0 = 127, i1 = 127;
    ARGM(x0, 4 * r,       m0, i0);
    ARGM(x1, 32 + 4 * r,  m0, i0);
    if (third) ARGM(x2, 64 + 4 * r, m0, i0);
    ARGM(y0, 4 * r,       m1, i1);
    ARGM(y1, 32 + 4 * r,  m1, i1);
    if (third) ARGM(y2, 64 + 4 * r, m1, i1);

#pragma unroll
    for (int o = 1; o < 8; o <<= 1) {
        float om0 = __shfl_xor_sync(0xffffffffu, m0, o);
        int   oi0 = __shfl_xor_sync(0xffffffffu, i0, o);
        float om1 = __shfl_xor_sync(0xffffffffu, m1, o);
        int   oi1 = __shfl_xor_sync(0xffffffffu, i1, o);
        if (om0 > m0 || (om0 == m0 && oi0 < i0)) { m0 = om0; i0 = oi0; }
        if (om1 > m1 || (om1 == m1 && oi1 < i1)) { m1 = om1; i1 = oi1; }
    }
    unsigned b0 = __float_as_uint(m0), b1 = __float_as_uint(m1);
    unsigned u0 = (m0 > 0.05f) ? ((b0 < 0x3F800000u) ? (0x3F800000u - b0) : 0u) : 0xFFFFFFFFu;
    unsigned u1 = (m1 > 0.05f) ? ((b1 < 0x3F800000u) ? (0x3F800000u - b1) : 0u) : 0xFFFFFFFFu;

    if (r == 0) {
        *reinterpret_cast<uint2*>(&g_keys[a0]) = make_uint2(u0, u1);
        *reinterpret_cast<unsigned short*>(&g_class[a0]) =
            (unsigned short)((unsigned)i0 | ((unsigned)i1 << 8));
    }

    unsigned msk0 = __ballot_sync(0xffffffffu, (r == 0) && u0 < 16380u);
    unsigned msk1 = __ballot_sync(0xffffffffu, (r == 0) && u1 < 16380u);
    unsigned tot = (unsigned)(__popc(msk0) + __popc(msk1));
    if (tot) {
        int b = a0 / An;
        int leader = __ffs(msk0 | msk1) - 1;
        unsigned base = 0;
        if ((threadIdx.x & 31) == leader) base = atomicAdd(&g_ccnt[b], tot);
        base = __shfl_sync(0xffffffffu, base, leader);
        if (r == 0) {
            unsigned lanebit = 1u << (threadIdx.x & 31);
            int al = a0 - b * An;
            if (u0 < 16380u) {
                unsigned p = base + (unsigned)__popc(msk0 & (lanebit - 1u));
                if (p < CAP) g_cand[b * CAP + p] = (u0 << 17) | (unsigned)al;
            }
            if (u1 < 16380u) {
                unsigned p = base + (unsigned)__popc(msk0)
                           + (unsigned)__popc(msk1 & (lanebit - 1u));
                if (p < CAP) g_cand[b * CAP + p] = (u1 << 17) | (unsigned)(al + 1);
            }
        }
    }
}

// ---------- kernel 2: fused select + hybrid sort + decode + chunked greedy NMS ----------
__global__ __launch_bounds__(1024) void k_post(const float4* __restrict__ reg,
                                               const float4* __restrict__ anc,
                                               float* __restrict__ out) {
    __shared__ __align__(16) unsigned hist[4096];   // aliased: sk32 / sk64
    __shared__ float4 sbox[1024];
    __shared__ float  sarea[1024];
    __shared__ unsigned wsum[32];
    __shared__ int s_cut;
    __shared__ unsigned s_tot, s_n;
    __shared__ unsigned s_rowmask[32], s_keptw[32];
    __shared__ unsigned s_chunksupp;
    __shared__ int s_kcnt;
    __shared__ int s_base[32];

    int b = blockIdx.x, tid = threadIdx.x;
    int lane = tid & 31, wid = tid >> 5;

    unsigned ccnt = g_ccnt[b];
    unsigned cc = (ccnt < (unsigned)CAP) ? ccnt : (unsigned)CAP;
    const unsigned* cand = g_cand + b * CAP;

    if (tid < MAXOBJ) {
        out[b * MAXOBJ + tid] = -1.f;
        out[Bn * MAXOBJ + b * MAXOBJ + tid] = -1.f;
    }
    if (tid < MAXOBJ * 4) out[2 * Bn * MAXOBJ + b * MAXOBJ * 4 + tid] = 0.f;

    for (int i = tid; i < 4096; i += 1024) hist[i] = 0u;
    if (tid == 0) { s_cut = -1; s_tot = 0u; s_n = 0u; s_kcnt = 0; }
    if (tid < 32) s_keptw[tid] = 0u;
    __syncthreads();

    for (unsigned c = tid; c < cc; c += 1024)
        atomicAdd(&hist[(cand[c] >> 17) >> 2], 1u);
    __syncthreads();

    unsigned h0 = hist[4 * tid], h1 = hist[4 * tid + 1],
             h2 = hist[4 * tid + 2], h3 = hist[4 * tid + 3];
    unsigned s = h0 + h1 + h2 + h3;
    unsigned x = s;
#pragma unroll
    for (int o = 1; o < 32; o <<= 1) {
        unsigned y = __shfl_up_sync(0xffffffffu, x, o);
        if (lane >= o) x += y;
    }
    if (lane == 31) wsum[wid] = x;
    __syncthreads();
    if (tid < 32) {
        unsigned v = wsum[tid];
#pragma unroll
        for (int o = 1; o < 32; o <<= 1) {
            unsigned y = __shfl_up_sync(0xffffffffu, v, o);
            if (tid >= o) v += y;
        }
        wsum[tid] = v;
    }
    __syncthreads();
    unsigned incl = x + (wid ? wsum[wid - 1] : 0u);
    unsigned excl = incl - s;
    if (excl < TOPN && incl >= TOPN) {
        int cut; unsigned c;
        if (excl + h0 >= TOPN)                { cut = 4 * tid;     c = excl + h0; }
        else if (excl + h0 + h1 >= TOPN)      { cut = 4 * tid + 1; c = excl + h0 + h1; }
        else if (excl + h0 + h1 + h2 >= TOPN) { cut = 4 * tid + 2; c = excl + h0 + h1 + h2; }
        else                                  { cut = 4 * tid + 3; c = excl + h0 + h1 + h2 + h3; }
        s_cut = cut; s_tot = c;
    }
    __syncthreads();

    bool fast = (s_cut >= 0) && (s_tot <= 1024u) && (ccnt <= (unsigned)CAP);
    unsigned* sk32 = hist;
    unsigned long long* sk64 = (unsigned long long*)hist;
    unsigned long long key = ~0ull;

    if (fast) {
        unsigned ulimit = ((unsigned)s_cut + 1u) << 2;
        for (unsigned c = tid; c < cc; c += 1024) {
            unsigned k2 = cand[c];
            bool sel = (k2 >> 17) < ulimit;
            unsigned am = __activemask();
            unsigned bal = __ballot_sync(am, sel);
            if (bal) {
                int leader = __ffs(bal) - 1;
                unsigned base = 0;
                if (lane == leader) base = atomicAdd(&s_n, (unsigned)__popc(bal));
                base = __shfl_sync(am, base, leader);
                if (sel) sk32[base + __popc(bal & ((1u << lane) - 1u))] = k2;
            }
        }
        __syncthreads();
        unsigned n = s_n;
        unsigned v = (tid < (int)n) ? sk32[tid] : 0xFFFFFFFFu;
        __syncthreads();
#pragma unroll
        for (int kk = 2; kk <= 32; kk <<= 1) {
            for (int j = kk >> 1; j > 0; j >>= 1) {
                unsigned o = __shfl_xor_sync(0xffffffffu, v, j);
                bool keepmin = ((tid & kk) == 0) == ((tid & j) == 0);
                v = keepmin ? (v < o ? v : o) : (v > o ? v : o);
            }
        }
        for (int kk = 64; kk <= 1024; kk <<= 1) {
            for (int j = kk >> 1; j >= 32; j >>= 1) {
                sk32[tid] = v;
                __syncthreads();
                unsigned o = sk32[tid ^ j];
                __syncthreads();
                bool keepmin = ((tid & kk) == 0) == ((tid & j) == 0);
                v = keepmin ? (v < o ? v : o) : (v > o ? v : o);
            }
#pragma unroll
            for (int j = 16; j > 0; j >>= 1) {
                unsigned o = __shfl_xor_sync(0xffffffffu, v, j);
                bool keepmin = ((tid & kk) == 0) == ((tid & j) == 0);
                v = keepmin ? (v < o ? v : o) : (v > o ? v : o);
            }
        }
        key = (unsigned long long)v;
    } else {
        const unsigned* keys = g_keys + (size_t)b * An;
        unsigned long long pref = 0ull;
        int rankNeed = TOPN;
        __shared__ unsigned s_c;
        for (int bit = 48; bit >= 0; --bit) {
            if (tid == 0) s_c = 0u;
            __syncthreads();
            unsigned c = 0;
            for (int a = tid; a < An; a += 1024) {
                unsigned long long k = ((unsigned long long)keys[a] << 17) | (unsigned)a;
                if ((k >> (bit + 1)) == pref && !((k >> bit) & 1ull)) c++;
            }
#pragma unroll
            for (int o = 16; o; o >>= 1) c += __shfl_down_sync(0xffffffffu, c, o);
            if (lane == 0) atomicAdd(&s_c, c);
            __syncthreads();
            unsigned C0 = s_c;
            if (rankNeed <= (int)C0) pref <<= 1;
            else { pref = (pref << 1) | 1ull; rankNeed -= (int)C0; }
            __syncthreads();
        }
        for (int a = tid; a < An; a += 1024) {
            unsigned long long k = ((unsigned long long)keys[a] << 17) | (unsigned)a;
            if (k <= pref) {
                unsigned p = atomicAdd(&s_n, 1u);
                if (p < 1024u) sk64[p] = k;
            }
        }
        __syncthreads();
        unsigned n = s_n;
        if ((unsigned)tid >= n) sk64[tid] = ~0ull;
        __syncthreads();
        for (int kk = 2; kk <= 1024; kk <<= 1) {
            for (int j = kk >> 1; j > 0; j >>= 1) {
                int ixj = tid ^ j;
                if (ixj > tid) {
                    unsigned long long a0 = sk64[tid], a1 = sk64[ixj];
                    bool asc = (tid & kk) == 0;
                    if (asc ? (a0 > a1) : (a0 < a1)) { sk64[tid] = a1; sk64[ixj] = a0; }
                }
                __syncthreads();
            }
        }
        key = sk64[tid];
    }

    // gather + decode into registers
    unsigned n_real = s_n;
    float sc = 0.f, clf = 0.f;
    float4 mybox = make_float4(0.f, 0.f, 0.f, 0.f);
    float myarea = 1e9f;
    if (tid < TOPN && (unsigned)tid < n_real) {
        int a = (int)(key & 0x1FFFFull);
        unsigned u = (unsigned)(key >> 17);
        sc = (u >= 0x3F800000u) ? 0.f : __uint_as_float(0x3F800000u - u);
        clf = (float)g_class[(size_t)b * An + a];

        float4 rg = __ldg(reg + (size_t)b * An + a);
        float4 an = __ldg(anc + (size_t)b * An + a);
        float aw  = __fsub_rn(an.z, an.x), ah = __fsub_rn(an.w, an.y);
        float acx = __fadd_rn(an.x, __fmul_rn(0.5f, aw));
        float acy = __fadd_rn(an.y, __fmul_rn(0.5f, ah));
        float pw  = __fmul_rn(expf(rg.z), aw);
        float ph  = __fmul_rn(expf(rg.w), ah);
        float pcx = __fadd_rn(__fmul_rn(rg.x, aw), acx);
        float pcy = __fadd_rn(__fmul_rn(rg.y, ah), acy);
        float hw  = __fmul_rn(0.5f, pw), hh = __fmul_rn(0.5f, ph);
        mybox.x = truncf(__fsub_rn(pcx, hw));
        mybox.y = truncf(__fsub_rn(pcy, hh));
        mybox.z = truncf(__fadd_rn(pcx, hw));
        mybox.w = truncf(__fadd_rn(pcy, hh));
        myarea = fmaxf(__fmul_rn(__fsub_rn(mybox.z, mybox.x), __fsub_rn(mybox.w, mybox.y)), 1e-4f);
        sbox[tid] = mybox;
        sarea[tid] = myarea;
    } else {
        sbox[tid] = make_float4(1e9f, 1e9f, 1e9f, 1e9f);
        sarea[tid] = 1e9f;
    }
    bool valid = (tid < TOPN) && (sc > 0.05f);
    bool supp = !valid;
    if (tid == 0) g_ccnt[b] = 0u;               // reset for next graph replay
    __syncthreads();

    // ---- chunked greedy NMS: 32 chunks of 32, early exit at MAXOBJ kept ----
    for (int c = 0; c < 32; ++c) {
        if (s_kcnt >= MAXOBJ) break;            // uniform (post-barrier view)
        int cbase = c << 5;
        // matrix phase: warp `wid` computes row `wid`: IoU(chunk box wid, chunk box lane)
        {
            float4 bw = sbox[cbase + wid]; float aw_ = sarea[cbase + wid];
            float4 bj = sbox[cbase + lane]; float aj = sarea[cbase + lane];
            bool hit = (lane > wid) && iou_ge(bw, aw_, bj, aj);
            unsigned row = __ballot_sync(0xffffffffu, hit);
            if (lane == 0) s_rowmask[wid] = row;
        }
        if (wid == c) {
            unsigned sb = __ballot_sync(0xffffffffu, supp);
            if (lane == 0) s_chunksupp = sb;
        }
        __syncthreads();
        // closure (computed redundantly per warp; consistent inputs)
        unsigned myrow = s_rowmask[lane];
        unsigned sup32 = s_chunksupp;
        unsigned kept32 = 0u;
#pragma unroll
        for (int t = 0; t < 32; ++t) {
            unsigned rowt = __shfl_sync(0xffffffffu, myrow, t);
            if (!((sup32 >> t) & 1u)) { kept32 |= (1u << t); sup32 |= rowt; }
        }
        // apply suppression
        if (wid == c) {
            supp = supp || !((kept32 >> lane) & 1u);
        } else if (wid > c && !supp) {
            unsigned kb = kept32;
            while (kb) {
                int t = __ffs(kb) - 1; kb &= kb - 1u;
                if (iou_ge(sbox[cbase + t], sarea[cbase + t], mybox, myarea)) { supp = true; break; }
            }
        }
        if (tid == 0) { s_keptw[c] = kept32; s_kcnt += __popc(kept32); }
        __syncthreads();
    }

    // prefix popcount of kept words
    if (tid < 32) {
        unsigned kw = s_keptw[lane];
        int c = __popc(kw), xx = c;
#pragma unroll
        for (int o = 1; o < 32; o <<= 1) {
            int y = __shfl_up_sync(0xffffffffu, xx, o);
            if (lane >= o) xx += y;
        }
        s_base[lane] = xx - c;
    }
    __syncthreads();

    if (tid < TOPN) {
        unsigned kw = s_keptw[wid];
        if ((kw >> lane) & 1u) {
            int r = s_base[wid] + __popc(kw & ((1u << lane) - 1u));
            if (r < MAXOBJ) {
                out[b * MAXOBJ + r] = sc;
                out[Bn * MAXOBJ + b * MAXOBJ + r] = clf;
                float* ob = out + 2 * Bn * MAXOBJ + (b * MAXOBJ + r) * 4;
                ob[0] = mybox.x; ob[1] = mybox.y; ob[2] = mybox.z; ob[3] = mybox.w;
            }
        }
    }
}

extern "C" void kernel_launch(void* const* d_in, const int* in_sizes, int n_in,
                              void* d_out, int out_size) {
    const float*  cls = (const float*)d_in[0];
    const float4* reg = (const float4*)d_in[1];
    const float4* anc = (const float4*)d_in[2];
    float* out = (float*)d_out;

    k_score<<<(Bn * An / 2 * 8) / 256, 256>>>((const float4*)cls);
    k_post<<<Bn, 1024>>>(reg, anc, out);
}

// round 12
// speedup vs baseline: 1.8324x; 1.0545x over previous
#include <cuda_runtime.h>
#include <math.h>

#define Bn 8
#define An 100000
#define Cn 80
#define TOPN 1000
#define MAXOBJ 100
#define CAP 32768

__device__ unsigned       g_keys[Bn * An];
__device__ unsigned char  g_class[Bn * An];
__device__ unsigned       g_cand[Bn * CAP];
__device__ unsigned       g_ccnt[Bn];        // zero-init; reset inside k_post

#define ARGM(v, base, m, mi) \
    do { \
        if ((v).x > (m)) { (m) = (v).x; (mi) = (base); } \
        if ((v).y > (m)) { (m) = (v).y; (mi) = (base) + 1; } \
        if ((v).z > (m)) { (m) = (v).z; (mi) = (base) + 2; } \
        if ((v).w > (m)) { (m) = (v).w; (mi) = (base) + 3; } \
    } while (0)

// exact: iou >= 0.5  <=>  3*inter >= ai+aj (all quantities integer-valued f32)
__device__ __forceinline__ bool iou_ge(float4 bi, float ai, float4 bj, float aj) {
    float tlx = fmaxf(bi.x, bj.x), tly = fmaxf(bi.y, bj.y);
    float brx = fminf(bi.z, bj.z), bry = fminf(bi.w, bj.w);
    float sx = fmaxf(__fsub_rn(brx, tlx), 0.f);
    float sy = fmaxf(__fsub_rn(bry, tly), 0.f);
    float inter = __fmul_rn(sx, sy);
    return __fmul_rn(3.f, inter) >= __fadd_rn(ai, aj);
}

// ---------- kernel 1: 2 anchors / 8 lanes, line-aligned loads (20 wf/warp, ideal) ----------
__global__ __launch_bounds__(256) void k_score(const float4* __restrict__ cls4) {
    int T = blockIdx.x * 256 + threadIdx.x;
    int g = T >> 3, r = T & 7;               // pair id, lane-in-group
    int a0 = g * 2;
    const float4* p = cls4 + (size_t)g * 40;  // pair base (640B, 5 lines)

    // load i covers 128B line i of the pair; all loads full-width & aligned
    float4 v0 = __ldcs(p + r);
    float4 v1 = __ldcs(p + 8 + r);
    float4 v2 = __ldcs(p + 16 + r);
    float4 v3 = __ldcs(p + 24 + r);
    float4 v4 = __ldcs(p + 32 + r);

    float m0 = -1.f, m1 = -1.f; int i0 = 127, i1 = 127;
    ARGM(v0, 4 * r,      m0, i0);             // anchor0 classes [0,32)
    ARGM(v1, 32 + 4 * r, m0, i0);             // anchor0 classes [32,64)
    if (r < 4) ARGM(v2, 64 + 4 * r, m0, i0);  // anchor0 classes [64,80)
    else       ARGM(v2, 4 * r - 16, m1, i1);  // anchor1 classes [0,16)
    ARGM(v3, 16 + 4 * r, m1, i1);             // anchor1 classes [16,48)
    ARGM(v4, 48 + 4 * r, m1, i1);             // anchor1 classes [48,80)

    // interleaved (val, first-idx) reduction over the 8-lane group
#pragma unroll
    for (int o = 1; o < 8; o <<= 1) {
        float om0 = __shfl_xor_sync(0xffffffffu, m0, o);
        int   oi0 = __shfl_xor_sync(0xffffffffu, i0, o);
        float om1 = __shfl_xor_sync(0xffffffffu, m1, o);
        int   oi1 = __shfl_xor_sync(0xffffffffu, i1, o);
        if (om0 > m0 || (om0 == m0 && oi0 < i0)) { m0 = om0; i0 = oi0; }
        if (om1 > m1 || (om1 == m1 && oi1 < i1)) { m1 = om1; i1 = oi1; }
    }
    unsigned b0 = __float_as_uint(m0), b1 = __float_as_uint(m1);
    unsigned u0 = (m0 > 0.05f) ? ((b0 < 0x3F800000u) ? (0x3F800000u - b0) : 0u) : 0xFFFFFFFFu;
    unsigned u1 = (m1 > 0.05f) ? ((b1 < 0x3F800000u) ? (0x3F800000u - b1) : 0u) : 0xFFFFFFFFu;

    if (r == 0) {
        *reinterpret_cast<uint2*>(&g_keys[a0]) = make_uint2(u0, u1);
        *reinterpret_cast<unsigned short*>(&g_class[a0]) =
            (unsigned short)((unsigned)i0 | ((unsigned)i1 << 8));
    }

    unsigned msk0 = __ballot_sync(0xffffffffu, (r == 0) && u0 < 16380u);
    unsigned msk1 = __ballot_sync(0xffffffffu, (r == 0) && u1 < 16380u);
    unsigned tot = (unsigned)(__popc(msk0) + __popc(msk1));
    if (tot) {
        int b = a0 / An;                      // warp = 4 pairs, never straddles images
        int leader = __ffs(msk0 | msk1) - 1;
        unsigned base = 0;
        if ((threadIdx.x & 31) == leader) base = atomicAdd(&g_ccnt[b], tot);
        base = __shfl_sync(0xffffffffu, base, leader);
        if (r == 0) {
            unsigned lanebit = 1u << (threadIdx.x & 31);
            int al = a0 - b * An;
            if (u0 < 16380u) {
                unsigned p2 = base + (unsigned)__popc(msk0 & (lanebit - 1u));
                if (p2 < CAP) g_cand[b * CAP + p2] = (u0 << 17) | (unsigned)al;
            }
            if (u1 < 16380u) {
                unsigned p2 = base + (unsigned)__popc(msk0)
                            + (unsigned)__popc(msk1 & (lanebit - 1u));
                if (p2 < CAP) g_cand[b * CAP + p2] = (u1 << 17) | (unsigned)(al + 1);
            }
        }
    }
}

// ---------- kernel 2: fused select + hybrid sort + decode + chunked greedy NMS ----------
__global__ __launch_bounds__(1024) void k_post(const float4* __restrict__ reg,
                                               const float4* __restrict__ anc,
                                               float* __restrict__ out) {
    __shared__ __align__(16) unsigned hist[4096];   // aliased: sk32 / sk64
    __shared__ float4 sbox[1024];
    __shared__ float  sarea[1024];
    __shared__ unsigned wsum[32];
    __shared__ int s_cut;
    __shared__ unsigned s_tot, s_n;
    __shared__ unsigned s_rowmask[32], s_keptw[32];
    __shared__ unsigned s_chunksupp;
    __shared__ int s_kcnt;
    __shared__ int s_base[32];

    int b = blockIdx.x, tid = threadIdx.x;
    int lane = tid & 31, wid = tid >> 5;

    unsigned ccnt = g_ccnt[b];
    unsigned cc = (ccnt < (unsigned)CAP) ? ccnt : (unsigned)CAP;
    const unsigned* cand = g_cand + b * CAP;

    if (tid < MAXOBJ) {
        out[b * MAXOBJ + tid] = -1.f;
        out[Bn * MAXOBJ + b * MAXOBJ + tid] = -1.f;
    }
    if (tid < MAXOBJ * 4) out[2 * Bn * MAXOBJ + b * MAXOBJ * 4 + tid] = 0.f;

    for (int i = tid; i < 4096; i += 1024) hist[i] = 0u;
    if (tid == 0) { s_cut = -1; s_tot = 0u; s_n = 0u; s_kcnt = 0; }
    if (tid < 32) s_keptw[tid] = 0u;
    __syncthreads();

    for (unsigned c = tid; c < cc; c += 1024)
        atomicAdd(&hist[(cand[c] >> 17) >> 2], 1u);
    __syncthreads();

    unsigned h0 = hist[4 * tid], h1 = hist[4 * tid + 1],
             h2 = hist[4 * tid + 2], h3 = hist[4 * tid + 3];
    unsigned s = h0 + h1 + h2 + h3;
    unsigned x = s;
#pragma unroll
    for (int o = 1; o < 32; o <<= 1) {
        unsigned y = __shfl_up_sync(0xffffffffu, x, o);
        if (lane >= o) x += y;
    }
    if (lane == 31) wsum[wid] = x;
    __syncthreads();
    if (tid < 32) {
        unsigned v = wsum[tid];
#pragma unroll
        for (int o = 1; o < 32; o <<= 1) {
            unsigned y = __shfl_up_sync(0xffffffffu, v, o);
            if (tid >= o) v += y;
        }
        wsum[tid] = v;
    }
    __syncthreads();
    unsigned incl = x + (wid ? wsum[wid - 1] : 0u);
    unsigned excl = incl - s;
    if (excl < TOPN && incl >= TOPN) {
        int cut; unsigned c;
        if (excl + h0 >= TOPN)                { cut = 4 * tid;     c = excl + h0; }
        else if (excl + h0 + h1 >= TOPN)      { cut = 4 * tid + 1; c = excl + h0 + h1; }
        else if (excl + h0 + h1 + h2 >= TOPN) { cut = 4 * tid + 2; c = excl + h0 + h1 + h2; }
        else                                  { cut = 4 * tid + 3; c = excl + h0 + h1 + h2 + h3; }
        s_cut = cut; s_tot = c;
    }
    __syncthreads();

    bool fast = (s_cut >= 0) && (s_tot <= 1024u) && (ccnt <= (unsigned)CAP);
    unsigned* sk32 = hist;
    unsigned long long* sk64 = (unsigned long long*)hist;
    unsigned long long key = ~0ull;

    if (fast) {
        unsigned ulimit = ((unsigned)s_cut + 1u) << 2;
        for (unsigned c = tid; c < cc; c += 1024) {
            unsigned k2 = cand[c];
            bool sel = (k2 >> 17) < ulimit;
            unsigned am = __activemask();
            unsigned bal = __ballot_sync(am, sel);
            if (bal) {
                int leader = __ffs(bal) - 1;
                unsigned base = 0;
                if (lane == leader) base = atomicAdd(&s_n, (unsigned)__popc(bal));
                base = __shfl_sync(am, base, leader);
                if (sel) sk32[base + __popc(bal & ((1u << lane) - 1u))] = k2;
            }
        }
        __syncthreads();
        unsigned n = s_n;
        unsigned v = (tid < (int)n) ? sk32[tid] : 0xFFFFFFFFu;
        __syncthreads();
#pragma unroll
        for (int kk = 2; kk <= 32; kk <<= 1) {
            for (int j = kk >> 1; j > 0; j >>= 1) {
                unsigned o = __shfl_xor_sync(0xffffffffu, v, j);
                bool keepmin = ((tid & kk) == 0) == ((tid & j) == 0);
                v = keepmin ? (v < o ? v : o) : (v > o ? v : o);
            }
        }
        for (int kk = 64; kk <= 1024; kk <<= 1) {
            for (int j = kk >> 1; j >= 32; j >>= 1) {
                sk32[tid] = v;
                __syncthreads();
                unsigned o = sk32[tid ^ j];
                __syncthreads();
                bool keepmin = ((tid & kk) == 0) == ((tid & j) == 0);
                v = keepmin ? (v < o ? v : o) : (v > o ? v : o);
            }
#pragma unroll
            for (int j = 16; j > 0; j >>= 1) {
                unsigned o = __shfl_xor_sync(0xffffffffu, v, j);
                bool keepmin = ((tid & kk) == 0) == ((tid & j) == 0);
                v = keepmin ? (v < o ? v : o) : (v > o ? v : o);
            }
        }
        key = (unsigned long long)v;
    } else {
        const unsigned* keys = g_keys + (size_t)b * An;
        unsigned long long pref = 0ull;
        int rankNeed = TOPN;
        __shared__ unsigned s_c;
        for (int bit = 48; bit >= 0; --bit) {
            if (tid == 0) s_c = 0u;
            __syncthreads();
            unsigned c = 0;
            for (int a = tid; a < An; a += 1024) {
                unsigned long long k = ((unsigned long long)keys[a] << 17) | (unsigned)a;
                if ((k >> (bit + 1)) == pref && !((k >> bit) & 1ull)) c++;
            }
#pragma unroll
            for (int o = 16; o; o >>= 1) c += __shfl_down_sync(0xffffffffu, c, o);
            if (lane == 0) atomicAdd(&s_c, c);
            __syncthreads();
            unsigned C0 = s_c;
            if (rankNeed <= (int)C0) pref <<= 1;
            else { pref = (pref << 1) | 1ull; rankNeed -= (int)C0; }
            __syncthreads();
        }
        for (int a = tid; a < An; a += 1024) {
            unsigned long long k = ((unsigned long long)keys[a] << 17) | (unsigned)a;
            if (k <= pref) {
                unsigned p = atomicAdd(&s_n, 1u);
                if (p < 1024u) sk64[p] = k;
            }
        }
        __syncthreads();
        unsigned n = s_n;
        if ((unsigned)tid >= n) sk64[tid] = ~0ull;
        __syncthreads();
        for (int kk = 2; kk <= 1024; kk <<= 1) {
            for (int j = kk >> 1; j > 0; j >>= 1) {
                int ixj = tid ^ j;
                if (ixj > tid) {
                    unsigned long long a0 = sk64[tid], a1 = sk64[ixj];
                    bool asc = (tid & kk) == 0;
                    if (asc ? (a0 > a1) : (a0 < a1)) { sk64[tid] = a1; sk64[ixj] = a0; }
                }
                __syncthreads();
            }
        }
        key = sk64[tid];
    }

    // gather + decode into registers
    unsigned n_real = s_n;
    float sc = 0.f, clf = 0.f;
    float4 mybox = make_float4(0.f, 0.f, 0.f, 0.f);
    float myarea = 1e9f;
    if (tid < TOPN && (unsigned)tid < n_real) {
        int a = (int)(key & 0x1FFFFull);
        unsigned u = (unsigned)(key >> 17);
        sc = (u >= 0x3F800000u) ? 0.f : __uint_as_float(0x3F800000u - u);
        clf = (float)g_class[(size_t)b * An + a];

        float4 rg = __ldg(reg + (size_t)b * An + a);
        float4 an = __ldg(anc + (size_t)b * An + a);
        float aw  = __fsub_rn(an.z, an.x), ah = __fsub_rn(an.w, an.y);
        float acx = __fadd_rn(an.x, __fmul_rn(0.5f, aw));
        float acy = __fadd_rn(an.y, __fmul_rn(0.5f, ah));
        float pw  = __fmul_rn(expf(rg.z), aw);
        float ph  = __fmul_rn(expf(rg.w), ah);
        float pcx = __fadd_rn(__fmul_rn(rg.x, aw), acx);
        float pcy = __fadd_rn(__fmul_rn(rg.y, ah), acy);
        float hw  = __fmul_rn(0.5f, pw), hh = __fmul_rn(0.5f, ph);
        mybox.x = truncf(__fsub_rn(pcx, hw));
        mybox.y = truncf(__fsub_rn(pcy, hh));
        mybox.z = truncf(__fadd_rn(pcx, hw));
        mybox.w = truncf(__fadd_rn(pcy, hh));
        myarea = fmaxf(__fmul_rn(__fsub_rn(mybox.z, mybox.x), __fsub_rn(mybox.w, mybox.y)), 1e-4f);
        sbox[tid] = mybox;
        sarea[tid] = myarea;
    } else {
        sbox[tid] = make_float4(1e9f, 1e9f, 1e9f, 1e9f);
        sarea[tid] = 1e9f;
    }
    bool valid = (tid < TOPN) && (sc > 0.05f);
    bool supp = !valid;
    if (tid == 0) g_ccnt[b] = 0u;               // reset for next graph replay
    __syncthreads();

    // ---- chunked greedy NMS: 32 chunks of 32, early exit at MAXOBJ kept ----
    for (int c = 0; c < 32; ++c) {
        if (s_kcnt >= MAXOBJ) break;            // uniform (post-barrier view)
        int cbase = c << 5;
        {
            float4 bw = sbox[cbase + wid]; float aw_ = sarea[cbase + wid];
            float4 bj = sbox[cbase + lane]; float aj = sarea[cbase + lane];
            bool hit = (lane > wid) && iou_ge(bw, aw_, bj, aj);
            unsigned row = __ballot_sync(0xffffffffu, hit);
            if (lane == 0) s_rowmask[wid] = row;
        }
        if (wid == c) {
            unsigned sb = __ballot_sync(0xffffffffu, supp);
            if (lane == 0) s_chunksupp = sb;
        }
        __syncthreads();
        unsigned myrow = s_rowmask[lane];
        unsigned sup32 = s_chunksupp;
        unsigned kept32 = 0u;
#pragma unroll
        for (int t = 0; t < 32; ++t) {
            unsigned rowt = __shfl_sync(0xffffffffu, myrow, t);
            if (!((sup32 >> t) & 1u)) { kept32 |= (1u << t); sup32 |= rowt; }
        }
        if (wid == c) {
            supp = supp || !((kept32 >> lane) & 1u);
        } else if (wid > c && !supp) {
            // fixed-trip, break-free: independent iterations -> pipelined LDS
            bool s2 = false;
#pragma unroll
            for (int t = 0; t < 32; ++t) {
                if ((kept32 >> t) & 1u)
                    s2 |= iou_ge(sbox[cbase + t], sarea[cbase + t], mybox, myarea);
            }
            supp = s2;
        }
        if (tid == 0) { s_keptw[c] = kept32; s_kcnt += __popc(kept32); }
        __syncthreads();
    }

    if (tid < 32) {
        unsigned kw = s_keptw[lane];
        int c = __popc(kw), xx = c;
#pragma unroll
        for (int o = 1; o < 32; o <<= 1) {
            int y = __shfl_up_sync(0xffffffffu, xx, o);
            if (lane >= o) xx += y;
        }
        s_base[lane] = xx - c;
    }
    __syncthreads();

    if (tid < TOPN) {
        unsigned kw = s_keptw[wid];
        if ((kw >> lane) & 1u) {
            int r = s_base[wid] + __popc(kw & ((1u << lane) - 1u));
            if (r < MAXOBJ) {
                out[b * MAXOBJ + r] = sc;
                out[Bn * MAXOBJ + b * MAXOBJ + r] = clf;
                float* ob = out + 2 * Bn * MAXOBJ + (b * MAXOBJ + r) * 4;
                ob[0] = mybox.x; ob[1] = mybox.y; ob[2] = mybox.z; ob[3] = mybox.w;
            }
        }
    }
}

extern "C" void kernel_launch(void* const* d_in, const int* in_sizes, int n_in,
                              void* d_out, int out_size) {
    const float*  cls = (const float*)d_in[0];
    const float4* reg = (const float4*)d_in[1];
    const float4* anc = (const float4*)d_in[2];
    float* out = (float*)d_out;

    k_score<<<(Bn * An / 2 * 8) / 256, 256>>>((const float4*)cls);
    k_post<<<Bn, 1024>>>(reg, anc, out);
}

// round 13
// speedup vs baseline: 1.9633x; 1.0714x over previous
#include <cuda_runtime.h>
#include <math.h>

#define Bn 8
#define An 100000
#define Cn 80
#define TOPN 1000
#define MAXOBJ 100
#define CAP 32768

__device__ unsigned       g_keys[Bn * An];
__device__ unsigned char  g_class[Bn * An];
__device__ unsigned       g_cand[Bn * CAP];
__device__ unsigned       g_ccnt[Bn];        // zero-init; reset inside k_post

#define ARGM(v, base, m, mi) \
    do { \
        if ((v).x > (m)) { (m) = (v).x; (mi) = (base); } \
        if ((v).y > (m)) { (m) = (v).y; (mi) = (base) + 1; } \
        if ((v).z > (m)) { (m) = (v).z; (mi) = (base) + 2; } \
        if ((v).w > (m)) { (m) = (v).w; (mi) = (base) + 3; } \
    } while (0)

// exact: iou >= 0.5  <=>  3*inter >= ai+aj (all quantities integer-valued f32)
__device__ __forceinline__ bool iou_ge(float4 bi, float ai, float4 bj, float aj) {
    float tlx = fmaxf(bi.x, bj.x), tly = fmaxf(bi.y, bj.y);
    float brx = fminf(bi.z, bj.z), bry = fminf(bi.w, bj.w);
    float sx = fmaxf(__fsub_rn(brx, tlx), 0.f);
    float sy = fmaxf(__fsub_rn(bry, tly), 0.f);
    float inter = __fmul_rn(sx, sy);
    return __fmul_rn(3.f, inter) >= __fadd_rn(ai, aj);
}

// ---------- kernel 1: 2 anchors / 8 lanes, line-aligned streaming loads ----------
__global__ __launch_bounds__(256) void k_score(const float4* __restrict__ cls4) {
    int T = blockIdx.x * 256 + threadIdx.x;
    int g = T >> 3, r = T & 7;
    int a0 = g * 2;
    const float4* p = cls4 + (size_t)g * 40;

    float4 v0 = __ldcs(p + r);
    float4 v1 = __ldcs(p + 8 + r);
    float4 v2 = __ldcs(p + 16 + r);
    float4 v3 = __ldcs(p + 24 + r);
    float4 v4 = __ldcs(p + 32 + r);

    float m0 = -1.f, m1 = -1.f; int i0 = 127, i1 = 127;
    ARGM(v0, 4 * r,      m0, i0);
    ARGM(v1, 32 + 4 * r, m0, i0);
    if (r < 4) ARGM(v2, 64 + 4 * r, m0, i0);
    else       ARGM(v2, 4 * r - 16, m1, i1);
    ARGM(v3, 16 + 4 * r, m1, i1);
    ARGM(v4, 48 + 4 * r, m1, i1);

#pragma unroll
    for (int o = 1; o < 8; o <<= 1) {
        float om0 = __shfl_xor_sync(0xffffffffu, m0, o);
        int   oi0 = __shfl_xor_sync(0xffffffffu, i0, o);
        float om1 = __shfl_xor_sync(0xffffffffu, m1, o);
        int   oi1 = __shfl_xor_sync(0xffffffffu, i1, o);
        if (om0 > m0 || (om0 == m0 && oi0 < i0)) { m0 = om0; i0 = oi0; }
        if (om1 > m1 || (om1 == m1 && oi1 < i1)) { m1 = om1; i1 = oi1; }
    }
    unsigned b0 = __float_as_uint(m0), b1 = __float_as_uint(m1);
    unsigned u0 = (m0 > 0.05f) ? ((b0 < 0x3F800000u) ? (0x3F800000u - b0) : 0u) : 0xFFFFFFFFu;
    unsigned u1 = (m1 > 0.05f) ? ((b1 < 0x3F800000u) ? (0x3F800000u - b1) : 0u) : 0xFFFFFFFFu;

    if (r == 0) {
        *reinterpret_cast<uint2*>(&g_keys[a0]) = make_uint2(u0, u1);
        *reinterpret_cast<unsigned short*>(&g_class[a0]) =
            (unsigned short)((unsigned)i0 | ((unsigned)i1 << 8));
    }

    unsigned msk0 = __ballot_sync(0xffffffffu, (r == 0) && u0 < 16380u);
    unsigned msk1 = __ballot_sync(0xffffffffu, (r == 0) && u1 < 16380u);
    unsigned tot = (unsigned)(__popc(msk0) + __popc(msk1));
    if (tot) {
        int b = a0 / An;
        int leader = __ffs(msk0 | msk1) - 1;
        unsigned base = 0;
        if ((threadIdx.x & 31) == leader) base = atomicAdd(&g_ccnt[b], tot);
        base = __shfl_sync(0xffffffffu, base, leader);
        if (r == 0) {
            unsigned lanebit = 1u << (threadIdx.x & 31);
            int al = a0 - b * An;
            if (u0 < 16380u) {
                unsigned p2 = base + (unsigned)__popc(msk0 & (lanebit - 1u));
                if (p2 < CAP) g_cand[b * CAP + p2] = (u0 << 17) | (unsigned)al;
            }
            if (u1 < 16380u) {
                unsigned p2 = base + (unsigned)__popc(msk0)
                            + (unsigned)__popc(msk1 & (lanebit - 1u));
                if (p2 < CAP) g_cand[b * CAP + p2] = (u1 << 17) | (unsigned)(al + 1);
            }
        }
    }
}

// ---------- kernel 2: fused select + hybrid sort + decode + lazy chunked greedy ----------
__global__ __launch_bounds__(1024) void k_post(const float4* __restrict__ reg,
                                               const float4* __restrict__ anc,
                                               float* __restrict__ out) {
    __shared__ __align__(16) unsigned hist[4096];   // aliased: sk32 / sk64
    __shared__ float4 sbox[1024];
    __shared__ float  sarea[1024];
    __shared__ unsigned wsum[32];
    __shared__ int s_cut;
    __shared__ unsigned s_tot, s_n;
    __shared__ unsigned s_keptw[32], s_invalid[32], s_cross[32];
    __shared__ int s_kcnt;
    __shared__ int s_base[32];

    int b = blockIdx.x, tid = threadIdx.x;
    int lane = tid & 31, wid = tid >> 5;

    unsigned ccnt = g_ccnt[b];
    unsigned cc = (ccnt < (unsigned)CAP) ? ccnt : (unsigned)CAP;
    const unsigned* cand = g_cand + b * CAP;

    if (tid < MAXOBJ) {
        out[b * MAXOBJ + tid] = -1.f;
        out[Bn * MAXOBJ + b * MAXOBJ + tid] = -1.f;
    }
    if (tid < MAXOBJ * 4) out[2 * Bn * MAXOBJ + b * MAXOBJ * 4 + tid] = 0.f;

    for (int i = tid; i < 4096; i += 1024) hist[i] = 0u;
    if (tid == 0) { s_cut = -1; s_tot = 0u; s_n = 0u; s_kcnt = 0; }
    if (tid < 32) s_keptw[tid] = 0u;
    __syncthreads();

    for (unsigned c = tid; c < cc; c += 1024)
        atomicAdd(&hist[(cand[c] >> 17) >> 2], 1u);
    __syncthreads();

    unsigned h0 = hist[4 * tid], h1 = hist[4 * tid + 1],
             h2 = hist[4 * tid + 2], h3 = hist[4 * tid + 3];
    unsigned s = h0 + h1 + h2 + h3;
    unsigned x = s;
#pragma unroll
    for (int o = 1; o < 32; o <<= 1) {
        unsigned y = __shfl_up_sync(0xffffffffu, x, o);
        if (lane >= o) x += y;
    }
    if (lane == 31) wsum[wid] = x;
    __syncthreads();
    if (tid < 32) {
        unsigned v = wsum[tid];
#pragma unroll
        for (int o = 1; o < 32; o <<= 1) {
            unsigned y = __shfl_up_sync(0xffffffffu, v, o);
            if (tid >= o) v += y;
        }
        wsum[tid] = v;
    }
    __syncthreads();
    unsigned incl = x + (wid ? wsum[wid - 1] : 0u);
    unsigned excl = incl - s;
    if (excl < TOPN && incl >= TOPN) {
        int cut; unsigned c;
        if (excl + h0 >= TOPN)                { cut = 4 * tid;     c = excl + h0; }
        else if (excl + h0 + h1 >= TOPN)      { cut = 4 * tid + 1; c = excl + h0 + h1; }
        else if (excl + h0 + h1 + h2 >= TOPN) { cut = 4 * tid + 2; c = excl + h0 + h1 + h2; }
        else                                  { cut = 4 * tid + 3; c = excl + h0 + h1 + h2 + h3; }
        s_cut = cut; s_tot = c;
    }
    __syncthreads();

    bool fast = (s_cut >= 0) && (s_tot <= 1024u) && (ccnt <= (unsigned)CAP);
    unsigned* sk32 = hist;
    unsigned long long* sk64 = (unsigned long long*)hist;
    unsigned long long key = ~0ull;

    if (fast) {
        unsigned ulimit = ((unsigned)s_cut + 1u) << 2;
        for (unsigned c = tid; c < cc; c += 1024) {
            unsigned k2 = cand[c];
            bool sel = (k2 >> 17) < ulimit;
            unsigned am = __activemask();
            unsigned bal = __ballot_sync(am, sel);
            if (bal) {
                int leader = __ffs(bal) - 1;
                unsigned base = 0;
                if (lane == leader) base = atomicAdd(&s_n, (unsigned)__popc(bal));
                base = __shfl_sync(am, base, leader);
                if (sel) sk32[base + __popc(bal & ((1u << lane) - 1u))] = k2;
            }
        }
        __syncthreads();
        unsigned n = s_n;
        unsigned v = (tid < (int)n) ? sk32[tid] : 0xFFFFFFFFu;
        __syncthreads();
#pragma unroll
        for (int kk = 2; kk <= 32; kk <<= 1) {
            for (int j = kk >> 1; j > 0; j >>= 1) {
                unsigned o = __shfl_xor_sync(0xffffffffu, v, j);
                bool keepmin = ((tid & kk) == 0) == ((tid & j) == 0);
                v = keepmin ? (v < o ? v : o) : (v > o ? v : o);
            }
        }
        for (int kk = 64; kk <= 1024; kk <<= 1) {
            for (int j = kk >> 1; j >= 32; j >>= 1) {
                sk32[tid] = v;
                __syncthreads();
                unsigned o = sk32[tid ^ j];
                __syncthreads();
                bool keepmin = ((tid & kk) == 0) == ((tid & j) == 0);
                v = keepmin ? (v < o ? v : o) : (v > o ? v : o);
            }
#pragma unroll
            for (int j = 16; j > 0; j >>= 1) {
                unsigned o = __shfl_xor_sync(0xffffffffu, v, j);
                bool keepmin = ((tid & kk) == 0) == ((tid & j) == 0);
                v = keepmin ? (v < o ? v : o) : (v > o ? v : o);
            }
        }
        key = (unsigned long long)v;
    } else {
        const unsigned* keys = g_keys + (size_t)b * An;
        unsigned long long pref = 0ull;
        int rankNeed = TOPN;
        __shared__ unsigned s_c;
        for (int bit = 48; bit >= 0; --bit) {
            if (tid == 0) s_c = 0u;
            __syncthreads();
            unsigned c = 0;
            for (int a = tid; a < An; a += 1024) {
                unsigned long long k = ((unsigned long long)keys[a] << 17) | (unsigned)a;
                if ((k >> (bit + 1)) == pref && !((k >> bit) & 1ull)) c++;
            }
#pragma unroll
            for (int o = 16; o; o >>= 1) c += __shfl_down_sync(0xffffffffu, c, o);
            if (lane == 0) atomicAdd(&s_c, c);
            __syncthreads();
            unsigned C0 = s_c;
            if (rankNeed <= (int)C0) pref <<= 1;
            else { pref = (pref << 1) | 1ull; rankNeed -= (int)C0; }
            __syncthreads();
        }
        for (int a = tid; a < An; a += 1024) {
            unsigned long long k = ((unsigned long long)keys[a] << 17) | (unsigned)a;
            if (k <= pref) {
                unsigned p = atomicAdd(&s_n, 1u);
                if (p < 1024u) sk64[p] = k;
            }
        }
        __syncthreads();
        unsigned n = s_n;
        if ((unsigned)tid >= n) sk64[tid] = ~0ull;
        __syncthreads();
        for (int kk = 2; kk <= 1024; kk <<= 1) {
            for (int j = kk >> 1; j > 0; j >>= 1) {
                int ixj = tid ^ j;
                if (ixj > tid) {
                    unsigned long long a0 = sk64[tid], a1 = sk64[ixj];
                    bool asc = (tid & kk) == 0;
                    if (asc ? (a0 > a1) : (a0 < a1)) { sk64[tid] = a1; sk64[ixj] = a0; }
                }
                __syncthreads();
            }
        }
        key = sk64[tid];
    }

    // gather + decode into registers
    unsigned n_real = s_n;
    float sc = 0.f, clf = 0.f;
    float4 mybox = make_float4(0.f, 0.f, 0.f, 0.f);
    float myarea = 1e9f;
    if (tid < TOPN && (unsigned)tid < n_real) {
        int a = (int)(key & 0x1FFFFull);
        unsigned u = (unsigned)(key >> 17);
        sc = (u >= 0x3F800000u) ? 0.f : __uint_as_float(0x3F800000u - u);
        clf = (float)g_class[(size_t)b * An + a];

        float4 rg = __ldg(reg + (size_t)b * An + a);
        float4 an = __ldg(anc + (size_t)b * An + a);
        float aw  = __fsub_rn(an.z, an.x), ah = __fsub_rn(an.w, an.y);
        float acx = __fadd_rn(an.x, __fmul_rn(0.5f, aw));
        float acy = __fadd_rn(an.y, __fmul_rn(0.5f, ah));
        float pw  = __fmul_rn(expf(rg.z), aw);
        float ph  = __fmul_rn(expf(rg.w), ah);
        float pcx = __fadd_rn(__fmul_rn(rg.x, aw), acx);
        float pcy = __fadd_rn(__fmul_rn(rg.y, ah), acy);
        float hw  = __fmul_rn(0.5f, pw), hh = __fmul_rn(0.5f, ph);
        mybox.x = truncf(__fsub_rn(pcx, hw));
        mybox.y = truncf(__fsub_rn(pcy, hh));
        mybox.z = truncf(__fadd_rn(pcx, hw));
        mybox.w = truncf(__fadd_rn(pcy, hh));
        myarea = fmaxf(__fmul_rn(__fsub_rn(mybox.z, mybox.x), __fsub_rn(mybox.w, mybox.y)), 1e-4f);
        sbox[tid] = mybox;
        sarea[tid] = myarea;
    } else {
        sbox[tid] = make_float4(1e9f, 1e9f, 1e9f, 1e9f);
        sarea[tid] = 1e9f;
    }
    bool valid = (tid < TOPN) && (sc > 0.05f);
    unsigned wm = __ballot_sync(0xffffffffu, valid);
    if (lane == 0) s_invalid[wid] = ~wm;      // chunk wid == warp wid
    if (tid == 0) g_ccnt[b] = 0u;             // reset for next graph replay
    __syncthreads();

    // ---- lazy chunked greedy NMS: suppression computed on demand per chunk ----
    for (int c = 0; c < 32; ++c) {
        if (s_kcnt >= MAXOBJ) break;            // uniform (post-barrier view)
        int cbase = c << 5;
        // lazy cross: warp w (< c) tests chunk-c box `lane` vs kept set of chunk w
        if (wid < c) {
            unsigned kb = s_keptw[wid];
            float4 bb = sbox[cbase + lane]; float ab = sarea[cbase + lane];
            bool hit = false;
            int wb = wid << 5;
#pragma unroll
            for (int t = 0; t < 32; ++t) {
                if ((kb >> t) & 1u)
                    hit |= iou_ge(sbox[wb + t], sarea[wb + t], bb, ab);
            }
            unsigned cw = __ballot_sync(0xffffffffu, hit);
            if (lane == 0) s_cross[wid] = cw;
        }
        // matrix phase: warp wid computes intra-chunk row wid
        {
            float4 bw = sbox[cbase + wid]; float aw_ = sarea[cbase + wid];
            float4 bj = sbox[cbase + lane]; float aj = sarea[cbase + lane];
            bool hit2 = (lane > wid) && iou_ge(bw, aw_, bj, aj);
            unsigned row = __ballot_sync(0xffffffffu, hit2);
            if (lane == 0) hist[2048 + wid] = row;   // rowmask scratch (hist free now)
        }
        __syncthreads();
        // closure (redundant per warp; consistent inputs)
        unsigned myrow = hist[2048 + lane];
        unsigned sup32 = s_invalid[c];
        for (int w = 0; w < c; ++w) sup32 |= s_cross[w];
        unsigned kept32 = 0u;
#pragma unroll
        for (int t = 0; t < 32; ++t) {
            unsigned rowt = __shfl_sync(0xffffffffu, myrow, t);
            if (!((sup32 >> t) & 1u)) { kept32 |= (1u << t); sup32 |= rowt; }
        }
        if (tid == 0) { s_keptw[c] = kept32; s_kcnt += __popc(kept32); }
        __syncthreads();
    }

    // prefix popcount of kept words
    if (tid < 32) {
        unsigned kw = s_keptw[lane];
        int c = __popc(kw), xx = c;
#pragma unroll
        for (int o = 1; o < 32; o <<= 1) {
            int y = __shfl_up_sync(0xffffffffu, xx, o);
            if (lane >= o) xx += y;
        }
        s_base[lane] = xx - c;
    }
    __syncthreads();

    if (tid < TOPN) {
        unsigned kw = s_keptw[wid];
        if ((kw >> lane) & 1u) {
            int r = s_base[wid] + __popc(kw & ((1u << lane) - 1u));
            if (r < MAXOBJ) {
                out[b * MAXOBJ + r] = sc;
                out[Bn * MAXOBJ + b * MAXOBJ + r] = clf;
                float* ob = out + 2 * Bn * MAXOBJ + (b * MAXOBJ + r) * 4;
                ob[0] = mybox.x; ob[1] = mybox.y; ob[2] = mybox.z; ob[3] = mybox.w;
            }
        }
    }
}

extern "C" void kernel_launch(void* const* d_in, const int* in_sizes, int n_in,
                              void* d_out, int out_size) {
    const float*  cls = (const float*)d_in[0];
    const float4* reg = (const float4*)d_in[1];
    const float4* anc = (const float4*)d_in[2];
    float* out = (float*)d_out;

    k_score<<<(Bn * An / 2 * 8) / 256, 256>>>((const float4*)cls);
    k_post<<<Bn, 1024>>>(reg, anc, out);
}